// round 12
// baseline (speedup 1.0000x reference)
#include <cuda_runtime.h>
#include <math.h>

#define BB 2
#define NN 8192
#define KNN 16
#define CIN 32
#define FULLW 0xffffffffu

// knn filter config
#define QPB 64      // queries per block
#define NSEG 4      // candidate segments (thread groups)
#define CAP 20      // buffer capacity per (query, segment)
#define FTILE 512   // candidates staged per tile

// ---------------- scratch ----------------
__device__ float  g_feat_t[BB*NN*CIN];
__device__ float4 g_nb[BB*NN*KNN]; // (nx, ny, nz, dist) per point per k, ascending
// weights, repacked by prep
__device__ float g_mlp1Wt[32*32];
__device__ float g_lse1We[3*32];
__device__ float g_lse1Wn[4*32];
__device__ float g_lse2We[3*32];
__device__ float g_lse2Wn[4*32];
__device__ float g_p1c1p[512];
__device__ float g_p1c2p[512];
__device__ float g_p1wmt[64*32];
__device__ float g_p2c1p[512];
__device__ float g_p2c2p[512];
__device__ float g_p2wmt[64*64];
__device__ float g_mlp2t[64*128];
__device__ float g_scWt[32*128];   // pre-scaled by sc_g*bns

// ---------------- prep: weights + feat transpose (coalesced reads) ----------------
__global__ void prep_all(
    const float* __restrict__ mlp1_W,
    const float* __restrict__ lse1_W,
    const float* __restrict__ lse2_W,
    const float* __restrict__ p1c1, const float* __restrict__ p1c2, const float* __restrict__ p1wm,
    const float* __restrict__ p2c1, const float* __restrict__ p2c2, const float* __restrict__ p2wm,
    const float* __restrict__ mlp2_W, const float* __restrict__ sc_W,
    const float* __restrict__ sc_g, const float* __restrict__ features)
{
    const float bns = rsqrtf(1.0f + 1e-5f);
    int t = threadIdx.x;
    int bid = blockIdx.x;
    if (bid < 11) {
        switch (bid) {
            case 0:
                for (int i = t; i < 32*32; i += 256) g_mlp1Wt[(i%32)*32 + (i/32)] = mlp1_W[i];
                break;
            case 1:
                if (t < 32) {
                    for (int d = 0; d < 3; d++) {
                        g_lse1We[d*32+t] = lse1_W[t*10+d]   + lse1_W[t*10+6+d];
                        g_lse1Wn[d*32+t] = lse1_W[t*10+3+d] - lse1_W[t*10+6+d];
                    }
                    g_lse1Wn[3*32+t] = lse1_W[t*10+9];
                }
                break;
            case 2:
                if (t < 32) {
                    for (int d = 0; d < 3; d++) {
                        g_lse2We[d*32+t] = lse2_W[t*10+d]   + lse2_W[t*10+6+d];
                        g_lse2Wn[d*32+t] = lse2_W[t*10+3+d] - lse2_W[t*10+6+d];
                    }
                    g_lse2Wn[3*32+t] = lse2_W[t*10+9];
                }
                break;
            case 3:
                for (int i = t; i < 512; i += 256) {
                    int j = i / 64, c = i % 64;
                    g_p1c1p[((c>>2)*8 + j)*4 + (c&3)] = p1c1[i];
                }
                break;
            case 4:
                for (int i = t; i < 512; i += 256) {
                    int r = i / 8, c = i % 8;
                    g_p1c2p[((c>>2)*64 + r)*4 + (c&3)] = p1c2[i];
                }
                break;
            case 5:
                for (int i = t; i < 32*64; i += 256) g_p1wmt[(i%64)*32 + (i/64)] = p1wm[i];
                break;
            case 6:
                for (int i = t; i < 512; i += 256) {
                    int j = i / 64, c = i % 64;
                    g_p2c1p[((c>>2)*8 + j)*4 + (c&3)] = p2c1[i];
                }
                break;
            case 7:
                for (int i = t; i < 512; i += 256) {
                    int r = i / 8, c = i % 8;
                    g_p2c2p[((c>>2)*64 + r)*4 + (c&3)] = p2c2[i];
                }
                break;
            case 8:
                for (int i = t; i < 64*64; i += 256) g_p2wmt[(i%64)*64 + (i/64)] = p2wm[i];
                break;
            case 9:
                for (int i = t; i < 128*64; i += 256) g_mlp2t[(i%64)*128 + (i/64)] = mlp2_W[i];
                break;
            default:
                for (int i = t; i < 128*32; i += 256) {
                    int oc = i / 32, d = i % 32;
                    g_scWt[d*128 + oc] = sc_W[i] * sc_g[oc] * bns;
                }
                break;
        }
        return;
    }
    bid -= 11;
    {   // feat transpose: gid linear over input layout (b, c, n) -> coalesced reads
        int gid = bid*256 + t;
        if (gid < BB*NN*CIN) {
            int b = gid / (CIN*NN);
            int rem = gid - b*CIN*NN;
            int c = rem / NN;
            int n = rem - c*NN;
            g_feat_t[((size_t)b*NN + n)*CIN + c] = features[gid];
        }
    }
}

// ---------------- bitonic helpers (fallback path) ----------------
__device__ __forceinline__ void bitonic32(float& key, int& pay, int lane) {
#pragma unroll
    for (int k = 2; k <= 32; k <<= 1) {
#pragma unroll
        for (int j = k >> 1; j > 0; j >>= 1) {
            float ok = __shfl_xor_sync(FULLW, key, j);
            int   op = __shfl_xor_sync(FULLW, pay, j);
            bool takeMin = (((lane & j) == 0) == ((lane & k) == 0));
            bool less = (ok < key) || (ok == key && op < pay);
            if (takeMin ? less : !less) { key = ok; pay = op; }
        }
    }
}

// warp-cooperative exact scan (fallback; proven R9-R11 machinery)
__device__ void exact_knn_warp(
    const float* __restrict__ cb, float qx, float qy, float qz,
    int lane, float& outLv, int& outLi)
{
    float lv = 3.4e38f; int li = 0x7fffffff;
    float tauV = 3.4e38f; int tauI = 0x7fffffff;
    bool seeded = false;
    for (int f = 0; f < NN; f += 32) {
        int j = f + lane;
        float x = cb[3*j], y = cb[3*j+1], z = cb[3*j+2];
        float dx = qx-x, dy = qy-y, dz = qz-z;
        float d2 = fmaf(dx, dx, fmaf(dy, dy, dz*dz));
        if (!seeded) {
            float key = d2; int pay = j;
            bitonic32(key, pay, lane);
            lv = (lane < 16) ? key : 3.4e38f;
            li = pay;
            tauV = __shfl_sync(FULLW, key, 15);
            tauI = __shfl_sync(FULLW, pay, 15);
            seeded = true;
            continue;
        }
        unsigned m = __ballot_sync(FULLW, (d2 < tauV) || (d2 == tauV && j < tauI));
        while (m) {
            int src = __ffs(m) - 1;
            m &= m - 1;
            float v  = __shfl_sync(FULLW, d2, src);
            int   vj = __shfl_sync(FULLW, j, src);
            if ((v < tauV) || (v == tauV && vj < tauI)) {
                unsigned le = __ballot_sync(FULLW,
                    (lane < 16) && ((lv < v) || (lv == v && li < vj)));
                int pos = __popc(le);
                float upv = __shfl_up_sync(FULLW, lv, 1);
                int   upi = __shfl_up_sync(FULLW, li, 1);
                if (lane == pos)                  { lv = v;   li = vj;  }
                else if (lane > pos && lane < 16) { lv = upv; li = upi; }
                tauV = __shfl_sync(FULLW, lv, 15);
                tauI = __shfl_sync(FULLW, li, 15);
            }
        }
    }
    outLv = lv; outLi = li;
}

// ---------------- KNN: branchless radius filter, thread-per-query ----------------
__global__ void __launch_bounds__(256) knn_filter(const float* __restrict__ coords) {
    __shared__ float4 tile[FTILE];
    __shared__ float          sd2[NSEG][CAP][QPB];
    __shared__ unsigned short sidx[NSEG][CAP][QPB];
    __shared__ int            scnt[NSEG][QPB];

    int tid = threadIdx.x;
    int b = blockIdx.y;
    int qbase = blockIdx.x * QPB;
    int ql = tid & (QPB-1);
    int seg = tid >> 6;
    int n = qbase + ql;
    const float* cb = coords + (size_t)b*NN*3;

    float qx = cb[n*3+0], qy = cb[n*3+1], qz = cb[n*3+2];
    float qsq = qx*qx + qy*qy + qz*qz;

    // per-query radius: target count ~30 from N(0,1) density, 2 corrections
    // R^3 = K / rho(r_eff), K = 3*30/(4pi), rho(r) = 8192*(2pi)^-1.5 * exp(-r^2/2)
    float rq = sqrtf(qsq);
    float R = cbrtf(0.013769f * expf(0.5f * qsq));
#pragma unroll
    for (int it = 0; it < 2; it++) {
        float re = fmaxf(rq - 0.5f*R, 0.f);
        R = cbrtf(0.013769f * expf(0.5f * re * re));
    }
    float tau = R*R - qsq;   // compare d2' = (|c|^2 - 2 q.c) < tau
    int cnt = 0;

    for (int t0 = 0; t0 < NN; t0 += FTILE) {
        __syncthreads();
        for (int u = tid; u < FTILE; u += 256) {
            int j = t0 + u;
            float x = cb[j*3+0], y = cb[j*3+1], z = cb[j*3+2];
            tile[u] = make_float4(-2.0f*x, -2.0f*y, -2.0f*z, x*x + y*y + z*z);
        }
        __syncthreads();

        int base = seg * (FTILE/NSEG);
#pragma unroll 4
        for (int e = 0; e < FTILE/NSEG; e++) {
            float4 c = tile[base + e];
            float d2 = fmaf(qx, c.x, fmaf(qy, c.y, fmaf(qz, c.z, c.w)));
            if (d2 < tau) {
                if (cnt < CAP) {
                    sd2[seg][cnt][ql] = d2;
                    sidx[seg][cnt][ql] = (unsigned short)(t0 + base + e);
                }
                cnt++;
            }
        }
    }
    scnt[seg][ql] = cnt;
    __syncthreads();

    // ---- selection (threads 0..63 = warps 0,1; one query each) ----
    bool flagged = false;
    if (tid < QPB) {
        int q = tid;
        int c0 = scnt[0][q], c1 = scnt[1][q], c2 = scnt[2][q], c3 = scnt[3][q];
        bool over = (c0 > CAP) | (c1 > CAP) | (c2 > CAP) | (c3 > CAP);
        int tot = c0 + c1 + c2 + c3;
        flagged = over || (tot < KNN);
        if (!flagged) {
            int cs[4] = {c0, c1, c2, c3};
#pragma unroll 1
            for (int r = 0; r < KNN; r++) {
                float best = 3.4e38f; int bi = 0x7fffffff;
                int bs = 0, be = 0;
                for (int s = 0; s < NSEG; s++) {
                    int lim = cs[s];
                    for (int e = 0; e < lim; e++) {
                        float d = sd2[s][e][q];
                        int j = sidx[s][e][q];
                        if ((d < best) || (d == best && j < bi)) {
                            best = d; bi = j; bs = s; be = e;
                        }
                    }
                }
                sd2[bs][be][q] = 3.4e38f;
                float nx = cb[bi*3+0], ny = cb[bi*3+1], nz = cb[bi*3+2];
                g_nb[((size_t)b*NN + n)*KNN + r] =
                    make_float4(nx, ny, nz, sqrtf(fmaxf(best + qsq, 0.f)));
            }
        }
    }

    // ---- fallback: warps 0,1 cooperatively rescan flagged queries exactly ----
    int warp = tid >> 5, lane = tid & 31;
    if (warp < 2) {
        unsigned fm = __ballot_sync(FULLW, flagged);
        while (fm) {
            int src = __ffs(fm) - 1;
            fm &= fm - 1;
            float fqx = __shfl_sync(FULLW, qx, src);
            float fqy = __shfl_sync(FULLW, qy, src);
            float fqz = __shfl_sync(FULLW, qz, src);
            int qn = qbase + warp*32 + src;
            float lv; int li;
            exact_knn_warp(cb, fqx, fqy, fqz, lane, lv, li);
            if (lane < KNN) {
                float nx = cb[li*3+0], ny = cb[li*3+1], nz = cb[li*3+2];
                g_nb[((size_t)b*NN + qn)*KNN + lane] =
                    make_float4(nx, ny, nz, sqrtf(lv));
            }
        }
    }
}

// ---------------- fused per-point pipeline (8 points per 256-thread block) ----------------
__device__ __forceinline__ float sigmoidf_(float x) { return 1.0f / (1.0f + expf(-x)); }

struct SArena {
    float4 nb[8][16];
    float  A[8][64];
    float  M[8][64];
    float  Hs[8][8];
    float  Sp[8][16];
    float  Fe8[32*8];
    float  F8[64*8];
    float  Out8[64*8];
    float  Part[4096];
};

template<int NOUT>
__device__ __forceinline__ void stage(
    SArena* s, float featv, float cx, float cy, float cz,
    const float* __restrict__ We, const float* __restrict__ Wn,
    const float* __restrict__ bl, const float* __restrict__ gl, const float* __restrict__ btl,
    const float* __restrict__ c1p, const float* __restrict__ c2p,
    const float* __restrict__ Ws,
    const float* __restrict__ Wmt, const float* __restrict__ bm,
    const float* __restrict__ gm,  const float* __restrict__ btm,
    int lane, int warp, int tid)
{
    const float bns = rsqrtf(1.0f + 1e-5f);
    float we0 = We[0*32+lane], we1 = We[1*32+lane], we2 = We[2*32+lane];
    float wn0 = Wn[0*32+lane], wn1 = Wn[1*32+lane], wn2 = Wn[2*32+lane], wn3 = Wn[3*32+lane];
    float scl = gl[lane]*bns, shb = btl[lane];
    float base = bl[lane];
    base = fmaf(we0, cx, fmaf(we1, cy, fmaf(we2, cz, base)));

    float e[16];
    float avg = 0.f, mx = -3.4e38f;
#pragma unroll
    for (int k = 0; k < 16; k++) {
        float4 nb = s->nb[warp][k];
        float v = fmaf(wn0, nb.x, fmaf(wn1, nb.y, fmaf(wn2, nb.z, fmaf(wn3, nb.w, base))));
        v = fmaxf(scl*v + shb, 0.f);
        e[k] = v;
        avg += v;
        mx = fmaxf(mx, v);
    }
    avg *= 0.0625f;
    s->A[warp][lane] = avg; s->A[warp][32 + lane] = featv;
    s->M[warp][lane] = mx;  s->M[warp][32 + lane] = featv;
    __syncwarp();

    {
        int j = lane & 7;
        int srcbit = (lane >> 3) & 1;
        int chalf = lane >> 4;
        const float* S = srcbit ? s->M[warp] : s->A[warp];
        float h = 0.f;
#pragma unroll
        for (int cq = 0; cq < 8; cq++) {
            int quad = chalf*8 + cq;
            float4 w4 = *reinterpret_cast<const float4*>(&c1p[(quad*8 + j)*4]);
            float4 a4 = *reinterpret_cast<const float4*>(&S[chalf*32 + cq*4]);
            h = fmaf(w4.x, a4.x, fmaf(w4.y, a4.y, fmaf(w4.z, a4.z, fmaf(w4.w, a4.w, h))));
        }
        h += __shfl_xor_sync(FULLW, h, 16);
        float h2 = fmaxf(h, 0.f);
        float hsv = h2 + __shfl_xor_sync(FULLW, h2, 8);
        if (lane < 8) s->Hs[warp][lane] = hsv;
    }
    __syncwarp();

    float4 hs0 = *reinterpret_cast<const float4*>(&s->Hs[warp][0]);
    float4 hs1 = *reinterpret_cast<const float4*>(&s->Hs[warp][4]);
    float a, b2;
    {
        float4 w0 = *reinterpret_cast<const float4*>(&c2p[lane*4]);
        float4 w1 = *reinterpret_cast<const float4*>(&c2p[(64 + lane)*4]);
        a = w0.x*hs0.x + w0.y*hs0.y + w0.z*hs0.z + w0.w*hs0.w
          + w1.x*hs1.x + w1.y*hs1.y + w1.z*hs1.z + w1.w*hs1.w;
        float4 v0 = *reinterpret_cast<const float4*>(&c2p[(32 + lane)*4]);
        float4 v1 = *reinterpret_cast<const float4*>(&c2p[(96 + lane)*4]);
        b2 = v0.x*hs0.x + v0.y*hs0.y + v0.z*hs0.z + v0.w*hs0.w
           + v1.x*hs1.x + v1.y*hs1.y + v1.z*hs1.z + v1.w*hs1.w;
    }
    float chA = sigmoidf_(a), chB = sigmoidf_(b2);
    float xf = featv * chB;

    float vs[16], vm[16];
#pragma unroll
    for (int k = 0; k < 16; k++) {
        float ek = e[k] * chA;
        e[k] = ek;
        vs[k] = ek + xf;
        vm[k] = fmaxf(ek, xf);
    }
    {
        bool up = (lane & 16);
#pragma unroll
        for (int i = 0; i < 8; i++) {
            float ss = up ? vs[i] : vs[i+8];
            float ks = up ? vs[i+8] : vs[i];
            vs[i] = ks + __shfl_xor_sync(FULLW, ss, 16);
            float sm2 = up ? vm[i] : vm[i+8];
            float km = up ? vm[i+8] : vm[i];
            vm[i] = fmaxf(km, __shfl_xor_sync(FULLW, sm2, 16));
        }
    }
    {
        bool up = (lane & 8);
#pragma unroll
        for (int i = 0; i < 4; i++) {
            float ss = up ? vs[i] : vs[i+4];
            float ks = up ? vs[i+4] : vs[i];
            vs[i] = ks + __shfl_xor_sync(FULLW, ss, 8);
            float sm2 = up ? vm[i] : vm[i+4];
            float km = up ? vm[i+4] : vm[i];
            vm[i] = fmaxf(km, __shfl_xor_sync(FULLW, sm2, 8));
        }
    }
    {
        bool up = (lane & 4);
#pragma unroll
        for (int i = 0; i < 2; i++) {
            float ss = up ? vs[i] : vs[i+2];
            float ks = up ? vs[i+2] : vs[i];
            vs[i] = ks + __shfl_xor_sync(FULLW, ss, 4);
            float sm2 = up ? vm[i] : vm[i+2];
            float km = up ? vm[i+2] : vm[i];
            vm[i] = fmaxf(km, __shfl_xor_sync(FULLW, sm2, 4));
        }
    }
    {
        bool up = (lane & 2);
        float ss = up ? vs[0] : vs[1];
        float ks = up ? vs[1] : vs[0];
        vs[0] = ks + __shfl_xor_sync(FULLW, ss, 2);
        float sm2 = up ? vm[0] : vm[1];
        float km = up ? vm[1] : vm[0];
        vm[0] = fmaxf(km, __shfl_xor_sync(FULLW, sm2, 2));
    }
    vs[0] += __shfl_xor_sync(FULLW, vs[0], 1);
    vm[0] = fmaxf(vm[0], __shfl_xor_sync(FULLW, vm[0], 1));

    float ws0 = Ws[0], ws1 = Ws[1];
    float sp = sigmoidf_(ws0 * vs[0] * (1.0f/64.0f) + ws1 * vm[0]);
    int kL = (((lane>>4)&1)<<3) | (((lane>>3)&1)<<2) | (((lane>>2)&1)<<1) | ((lane>>1)&1);
    if (!(lane & 1)) s->Sp[warp][kL] = sp;
    float sps = sp;
#pragma unroll
    for (int off = 16; off > 0; off >>= 1) sps += __shfl_xor_sync(FULLW, sps, off);
    sps *= 0.5f;
    __syncwarp();

    float fA = 0.f;
#pragma unroll
    for (int k = 0; k < 16; k++) fA = fmaf(e[k], s->Sp[warp][k], fA);

    s->F8[lane*8 + warp]        = fA;
    s->F8[(32 + lane)*8 + warp] = xf * sps;
    __syncthreads();

    constexpr int G = NOUT/32;
    {
        float acc[G][8];
#pragma unroll
        for (int g = 0; g < G; g++)
#pragma unroll
            for (int p = 0; p < 8; p++) acc[g][p] = 0.f;
        int jb = warp * 8;
#pragma unroll
        for (int jj = 0; jj < 8; jj++) {
            int j = jb + jj;
            float4 a0 = *reinterpret_cast<const float4*>(&s->F8[j*8]);
            float4 a1 = *reinterpret_cast<const float4*>(&s->F8[j*8+4]);
#pragma unroll
            for (int g = 0; g < G; g++) {
                float wv = Wmt[j*NOUT + g*32 + lane];
                acc[g][0] = fmaf(wv, a0.x, acc[g][0]);
                acc[g][1] = fmaf(wv, a0.y, acc[g][1]);
                acc[g][2] = fmaf(wv, a0.z, acc[g][2]);
                acc[g][3] = fmaf(wv, a0.w, acc[g][3]);
                acc[g][4] = fmaf(wv, a1.x, acc[g][4]);
                acc[g][5] = fmaf(wv, a1.y, acc[g][5]);
                acc[g][6] = fmaf(wv, a1.z, acc[g][6]);
                acc[g][7] = fmaf(wv, a1.w, acc[g][7]);
            }
        }
#pragma unroll
        for (int g = 0; g < G; g++) {
            int bidx = (warp*NOUT + g*32 + lane)*8;
            *reinterpret_cast<float4*>(&s->Part[bidx])   = make_float4(acc[g][0], acc[g][1], acc[g][2], acc[g][3]);
            *reinterpret_cast<float4*>(&s->Part[bidx+4]) = make_float4(acc[g][4], acc[g][5], acc[g][6], acc[g][7]);
        }
    }
    __syncthreads();

#pragma unroll
    for (int g = 0; g < G; g++) {
        int idx = g*256 + tid;
        int oc = idx >> 3, pp = idx & 7;
        float sum = 0.f;
#pragma unroll
        for (int w = 0; w < 8; w++) sum += s->Part[(w*NOUT + oc)*8 + pp];
        sum += bm[oc];
        s->Out8[idx] = fmaxf(gm[oc]*bns*sum + btm[oc], 0.f);
    }
    __syncthreads();
}

__global__ void __launch_bounds__(256) fused_kernel(
    const float* __restrict__ coords,
    const float* __restrict__ mlp1_b,
    const float* __restrict__ lse1_b, const float* __restrict__ lse1_g, const float* __restrict__ lse1_bt,
    const float* __restrict__ p1_Ws,  const float* __restrict__ p1_bm,  const float* __restrict__ p1_g, const float* __restrict__ p1_bt,
    const float* __restrict__ lse2_b, const float* __restrict__ lse2_g, const float* __restrict__ lse2_bt,
    const float* __restrict__ p2_Ws,  const float* __restrict__ p2_bm,  const float* __restrict__ p2_g, const float* __restrict__ p2_bt,
    const float* __restrict__ mlp2_b,
    const float* __restrict__ sc_b, const float* __restrict__ sc_g, const float* __restrict__ sc_bt,
    float* __restrict__ out)
{
    __shared__ SArena s;

    int tid = threadIdx.x;
    int warp = tid >> 5, lane = tid & 31;
    int p = blockIdx.x * 8 + warp;
    int b = p >> 13, n = p & (NN - 1);

    s.Fe8[lane*8 + warp] = g_feat_t[p*CIN + lane];

    const float* cb = coords + ((size_t)b*NN + n)*3;
    float cx = cb[0], cy = cb[1], cz = cb[2];
    if (lane < 16) {
        s.nb[warp][lane] = g_nb[(size_t)p*KNN + lane];
    }
    __syncwarp();

    float x1;
    {
        float acc = mlp1_b[lane];
#pragma unroll
        for (int d = 0; d < 32; d++) acc = fmaf(g_mlp1Wt[d*32 + lane], s.Fe8[d*8 + warp], acc);
        x1 = acc >= 0.f ? acc : 0.2f*acc;
    }

    stage<32>(&s, x1, cx, cy, cz, g_lse1We, g_lse1Wn, lse1_b, lse1_g, lse1_bt,
              g_p1c1p, g_p1c2p, p1_Ws, g_p1wmt, p1_bm, p1_g, p1_bt, lane, warp, tid);
    float o1 = s.Out8[lane*8 + warp];

    stage<64>(&s, o1, cx, cy, cz, g_lse2We, g_lse2Wn, lse2_b, lse2_g, lse2_bt,
              g_p2c1p, g_p2c2p, p2_Ws, g_p2wmt, p2_bm, p2_g, p2_bt, lane, warp, tid);

    {
        int slice = tid >> 6;
        int oc0 = (tid & 63) * 2;
        float acc0[8], acc1[8];
#pragma unroll
        for (int q = 0; q < 8; q++) { acc0[q] = 0.f; acc1[q] = 0.f; }
#pragma unroll
        for (int jj = 0; jj < 16; jj++) {
            int j = slice*16 + jj;
            float2 w2 = *reinterpret_cast<const float2*>(&g_mlp2t[j*128 + oc0]);
            float4 a0 = *reinterpret_cast<const float4*>(&s.Out8[j*8]);
            float4 a1 = *reinterpret_cast<const float4*>(&s.Out8[j*8+4]);
            acc0[0] = fmaf(w2.x, a0.x, acc0[0]); acc1[0] = fmaf(w2.y, a0.x, acc1[0]);
            acc0[1] = fmaf(w2.x, a0.y, acc0[1]); acc1[1] = fmaf(w2.y, a0.y, acc1[1]);
            acc0[2] = fmaf(w2.x, a0.z, acc0[2]); acc1[2] = fmaf(w2.y, a0.z, acc1[2]);
            acc0[3] = fmaf(w2.x, a0.w, acc0[3]); acc1[3] = fmaf(w2.y, a0.w, acc1[3]);
            acc0[4] = fmaf(w2.x, a1.x, acc0[4]); acc1[4] = fmaf(w2.y, a1.x, acc1[4]);
            acc0[5] = fmaf(w2.x, a1.y, acc0[5]); acc1[5] = fmaf(w2.y, a1.y, acc1[5]);
            acc0[6] = fmaf(w2.x, a1.z, acc0[6]); acc1[6] = fmaf(w2.y, a1.z, acc1[6]);
            acc0[7] = fmaf(w2.x, a1.w, acc0[7]); acc1[7] = fmaf(w2.y, a1.w, acc1[7]);
        }
#pragma unroll
        for (int dd = 0; dd < 8; dd++) {
            int d = slice*8 + dd;
            float2 w2 = *reinterpret_cast<const float2*>(&g_scWt[d*128 + oc0]);
            float4 f0 = *reinterpret_cast<const float4*>(&s.Fe8[d*8]);
            float4 f1 = *reinterpret_cast<const float4*>(&s.Fe8[d*8+4]);
            acc0[0] = fmaf(w2.x, f0.x, acc0[0]); acc1[0] = fmaf(w2.y, f0.x, acc1[0]);
            acc0[1] = fmaf(w2.x, f0.y, acc0[1]); acc1[1] = fmaf(w2.y, f0.y, acc1[1]);
            acc0[2] = fmaf(w2.x, f0.z, acc0[2]); acc1[2] = fmaf(w2.y, f0.z, acc1[2]);
            acc0[3] = fmaf(w2.x, f0.w, acc0[3]); acc1[3] = fmaf(w2.y, f0.w, acc1[3]);
            acc0[4] = fmaf(w2.x, f1.x, acc0[4]); acc1[4] = fmaf(w2.y, f1.x, acc1[4]);
            acc0[5] = fmaf(w2.x, f1.y, acc0[5]); acc1[5] = fmaf(w2.y, f1.y, acc1[5]);
            acc0[6] = fmaf(w2.x, f1.z, acc0[6]); acc1[6] = fmaf(w2.y, f1.z, acc1[6]);
            acc0[7] = fmaf(w2.x, f1.w, acc0[7]); acc1[7] = fmaf(w2.y, f1.w, acc1[7]);
        }
        int b0 = (slice*128 + oc0)*8;
        *reinterpret_cast<float4*>(&s.Part[b0])     = make_float4(acc0[0], acc0[1], acc0[2], acc0[3]);
        *reinterpret_cast<float4*>(&s.Part[b0+4])   = make_float4(acc0[4], acc0[5], acc0[6], acc0[7]);
        *reinterpret_cast<float4*>(&s.Part[b0+8])   = make_float4(acc1[0], acc1[1], acc1[2], acc1[3]);
        *reinterpret_cast<float4*>(&s.Part[b0+12])  = make_float4(acc1[4], acc1[5], acc1[6], acc1[7]);
    }
    __syncthreads();

    {
        const float bns = rsqrtf(1.0f + 1e-5f);
        int oc = tid & 127;
        int ph = tid >> 7;
        float4 v = make_float4(0.f, 0.f, 0.f, 0.f);
#pragma unroll
        for (int sl = 0; sl < 4; sl++) {
            float4 t = *reinterpret_cast<const float4*>(&s.Part[(sl*128 + oc)*8 + ph*4]);
            v.x += t.x; v.y += t.y; v.z += t.z; v.w += t.w;
        }
        float basev = mlp2_b[oc] + sc_g[oc]*bns*sc_b[oc] + sc_bt[oc];
        v.x += basev; v.y += basev; v.z += basev; v.w += basev;
        v.x = v.x >= 0.f ? v.x : 0.01f*v.x;
        v.y = v.y >= 0.f ? v.y : 0.01f*v.y;
        v.z = v.z >= 0.f ? v.z : 0.01f*v.z;
        v.w = v.w >= 0.f ? v.w : 0.01f*v.w;

        int p0 = blockIdx.x * 8;
        int b0 = p0 >> 13, n0 = p0 & (NN - 1);
        *reinterpret_cast<float4*>(&out[((size_t)(b0*128 + oc))*NN + n0 + ph*4]) = v;
    }
}

// ---------------- launch ----------------
extern "C" void kernel_launch(void* const* d_in, const int* in_sizes, int n_in,
                              void* d_out, int out_size) {
    const float* coords   = (const float*)d_in[0];
    const float* features = (const float*)d_in[1];
    const float* mlp1_W = (const float*)d_in[2];
    const float* mlp1_b = (const float*)d_in[3];
    const float* lse1_W = (const float*)d_in[4];
    const float* lse1_b = (const float*)d_in[5];
    const float* lse1_g = (const float*)d_in[6];
    const float* lse1_bt = (const float*)d_in[7];
    const float* p1_Wc1 = (const float*)d_in[8];
    const float* p1_Wc2 = (const float*)d_in[9];
    const float* p1_Ws  = (const float*)d_in[10];
    const float* p1_Wm  = (const float*)d_in[11];
    const float* p1_bm  = (const float*)d_in[12];
    const float* p1_g   = (const float*)d_in[13];
    const float* p1_bt  = (const float*)d_in[14];
    const float* lse2_W = (const float*)d_in[15];
    const float* lse2_b = (const float*)d_in[16];
    const float* lse2_g = (const float*)d_in[17];
    const float* lse2_bt = (const float*)d_in[18];
    const float* p2_Wc1 = (const float*)d_in[19];
    const float* p2_Wc2 = (const float*)d_in[20];
    const float* p2_Ws  = (const float*)d_in[21];
    const float* p2_Wm  = (const float*)d_in[22];
    const float* p2_bm  = (const float*)d_in[23];
    const float* p2_g   = (const float*)d_in[24];
    const float* p2_bt  = (const float*)d_in[25];
    const float* mlp2_W = (const float*)d_in[26];
    const float* mlp2_b = (const float*)d_in[27];
    const float* sc_W   = (const float*)d_in[28];
    const float* sc_b   = (const float*)d_in[29];
    const float* sc_g   = (const float*)d_in[30];
    const float* sc_bt  = (const float*)d_in[31];
    float* out = (float*)d_out;

    int prep_blocks = 11 + (BB*NN*CIN + 255)/256;
    prep_all<<<prep_blocks, 256>>>(mlp1_W, lse1_W, lse2_W, p1_Wc1, p1_Wc2, p1_Wm,
                                   p2_Wc1, p2_Wc2, p2_Wm, mlp2_W, sc_W, sc_g, features);
    knn_filter<<<dim3(NN/QPB, BB), 256>>>(coords);
    fused_kernel<<<(BB*NN)/8, 256>>>(coords, mlp1_b, lse1_b, lse1_g, lse1_bt,
                                     p1_Ws, p1_bm, p1_g, p1_bt,
                                     lse2_b, lse2_g, lse2_bt,
                                     p2_Ws, p2_bm, p2_g, p2_bt,
                                     mlp2_b, sc_b, sc_g, sc_bt, out);
}

// round 13
// speedup vs baseline: 2.4408x; 2.4408x over previous
#include <cuda_runtime.h>
#include <math.h>

#define BB 2
#define NN 8192
#define KNN 16
#define CIN 32
#define FULLW 0xffffffffu

// knn filter config
#define QPB 32      // queries per block
#define NSEG 8      // candidate segments (one warp-group of lanes per seg)
#define CAP 16      // buffer capacity per (query, segment)
#define ROWW (NSEG*CAP + 1)   // 129: padded row, 129 % 32 == 1 -> conflict-free
#define FTILE 1024  // candidates staged per tile

// ---------------- scratch ----------------
__device__ float  g_feat_t[BB*NN*CIN];
__device__ float4 g_nb[BB*NN*KNN]; // (nx, ny, nz, dist) per point per k, ascending
// weights, repacked by prep
__device__ float g_mlp1Wt[32*32];
__device__ float g_lse1We[3*32];
__device__ float g_lse1Wn[4*32];
__device__ float g_lse2We[3*32];
__device__ float g_lse2Wn[4*32];
__device__ float g_p1c1p[512];
__device__ float g_p1c2p[512];
__device__ float g_p1wmt[64*32];
__device__ float g_p2c1p[512];
__device__ float g_p2c2p[512];
__device__ float g_p2wmt[64*64];
__device__ float g_mlp2t[64*128];
__device__ float g_scWt[32*128];   // pre-scaled by sc_g*bns

// ---------------- prep: weights + feat transpose ----------------
__global__ void prep_all(
    const float* __restrict__ mlp1_W,
    const float* __restrict__ lse1_W,
    const float* __restrict__ lse2_W,
    const float* __restrict__ p1c1, const float* __restrict__ p1c2, const float* __restrict__ p1wm,
    const float* __restrict__ p2c1, const float* __restrict__ p2c2, const float* __restrict__ p2wm,
    const float* __restrict__ mlp2_W, const float* __restrict__ sc_W,
    const float* __restrict__ sc_g, const float* __restrict__ features)
{
    const float bns = rsqrtf(1.0f + 1e-5f);
    int t = threadIdx.x;
    int bid = blockIdx.x;
    if (bid < 11) {
        switch (bid) {
            case 0:
                for (int i = t; i < 32*32; i += 256) g_mlp1Wt[(i%32)*32 + (i/32)] = mlp1_W[i];
                break;
            case 1:
                if (t < 32) {
                    for (int d = 0; d < 3; d++) {
                        g_lse1We[d*32+t] = lse1_W[t*10+d]   + lse1_W[t*10+6+d];
                        g_lse1Wn[d*32+t] = lse1_W[t*10+3+d] - lse1_W[t*10+6+d];
                    }
                    g_lse1Wn[3*32+t] = lse1_W[t*10+9];
                }
                break;
            case 2:
                if (t < 32) {
                    for (int d = 0; d < 3; d++) {
                        g_lse2We[d*32+t] = lse2_W[t*10+d]   + lse2_W[t*10+6+d];
                        g_lse2Wn[d*32+t] = lse2_W[t*10+3+d] - lse2_W[t*10+6+d];
                    }
                    g_lse2Wn[3*32+t] = lse2_W[t*10+9];
                }
                break;
            case 3:
                for (int i = t; i < 512; i += 256) {
                    int j = i / 64, c = i % 64;
                    g_p1c1p[((c>>2)*8 + j)*4 + (c&3)] = p1c1[i];
                }
                break;
            case 4:
                for (int i = t; i < 512; i += 256) {
                    int r = i / 8, c = i % 8;
                    g_p1c2p[((c>>2)*64 + r)*4 + (c&3)] = p1c2[i];
                }
                break;
            case 5:
                for (int i = t; i < 32*64; i += 256) g_p1wmt[(i%64)*32 + (i/64)] = p1wm[i];
                break;
            case 6:
                for (int i = t; i < 512; i += 256) {
                    int j = i / 64, c = i % 64;
                    g_p2c1p[((c>>2)*8 + j)*4 + (c&3)] = p2c1[i];
                }
                break;
            case 7:
                for (int i = t; i < 512; i += 256) {
                    int r = i / 8, c = i % 8;
                    g_p2c2p[((c>>2)*64 + r)*4 + (c&3)] = p2c2[i];
                }
                break;
            case 8:
                for (int i = t; i < 64*64; i += 256) g_p2wmt[(i%64)*64 + (i/64)] = p2wm[i];
                break;
            case 9:
                for (int i = t; i < 128*64; i += 256) g_mlp2t[(i%64)*128 + (i/64)] = mlp2_W[i];
                break;
            default:
                for (int i = t; i < 128*32; i += 256) {
                    int oc = i / 32, d = i % 32;
                    g_scWt[d*128 + oc] = sc_W[i] * sc_g[oc] * bns;
                }
                break;
        }
        return;
    }
    bid -= 11;
    {   // feat transpose
        int gid = bid*256 + t;
        if (gid < BB*NN*CIN) {
            int b = gid / (CIN*NN);
            int rem = gid - b*CIN*NN;
            int c = rem / NN;
            int n = rem - c*NN;
            g_feat_t[((size_t)b*NN + n)*CIN + c] = features[gid];
        }
    }
}

// ---------------- bitonic helpers ----------------
__device__ __forceinline__ void bitonic32(float& key, int& pay, int lane) {
#pragma unroll
    for (int k = 2; k <= 32; k <<= 1) {
#pragma unroll
        for (int j = k >> 1; j > 0; j >>= 1) {
            float ok = __shfl_xor_sync(FULLW, key, j);
            int   op = __shfl_xor_sync(FULLW, pay, j);
            bool takeMin = (((lane & j) == 0) == ((lane & k) == 0));
            bool less = (ok < key) || (ok == key && op < pay);
            if (takeMin ? less : !less) { key = ok; pay = op; }
        }
    }
}

// merge sorted top-16 (lanes 0..15 of lv/li, ascending) with sorted-asc 32-chunk
__device__ __forceinline__ void merge_chunk(
    float key, int pay, float& lv, int& li, int lane)
{
    float ck = __shfl_xor_sync(FULLW, key, 31);
    int   cp = __shfl_xor_sync(FULLW, pay, 31);
    float v  = (lane < 16) ? lv : ck;
    int   vp = (lane < 16) ? li : cp;
#pragma unroll
    for (int j = 16; j > 0; j >>= 1) {
        float ov  = __shfl_xor_sync(FULLW, v, j);
        int   ovp = __shfl_xor_sync(FULLW, vp, j);
        bool takeMin = ((lane & j) == 0);
        bool less = (ov < v) || (ov == v && ovp < vp);
        if (takeMin ? less : !less) { v = ov; vp = ovp; }
    }
    lv = v; li = vp;
}

// warp-cooperative exact scan (fallback; proven R9-R12 machinery)
__device__ void exact_knn_warp(
    const float* __restrict__ cb, float qx, float qy, float qz,
    int lane, float& outLv, int& outLi)
{
    float lv = 3.4e38f; int li = 0x7fffffff;
    float tauV = 3.4e38f; int tauI = 0x7fffffff;
    bool seeded = false;
    for (int f = 0; f < NN; f += 32) {
        int j = f + lane;
        float x = cb[3*j], y = cb[3*j+1], z = cb[3*j+2];
        float dx = qx-x, dy = qy-y, dz = qz-z;
        float d2 = fmaf(dx, dx, fmaf(dy, dy, dz*dz));
        if (!seeded) {
            float key = d2; int pay = j;
            bitonic32(key, pay, lane);
            lv = (lane < 16) ? key : 3.4e38f;
            li = pay;
            tauV = __shfl_sync(FULLW, key, 15);
            tauI = __shfl_sync(FULLW, pay, 15);
            seeded = true;
            continue;
        }
        unsigned m = __ballot_sync(FULLW, (d2 < tauV) || (d2 == tauV && j < tauI));
        while (m) {
            int src = __ffs(m) - 1;
            m &= m - 1;
            float v  = __shfl_sync(FULLW, d2, src);
            int   vj = __shfl_sync(FULLW, j, src);
            if ((v < tauV) || (v == tauV && vj < tauI)) {
                unsigned le = __ballot_sync(FULLW,
                    (lane < 16) && ((lv < v) || (lv == v && li < vj)));
                int pos = __popc(le);
                float upv = __shfl_up_sync(FULLW, lv, 1);
                int   upi = __shfl_up_sync(FULLW, li, 1);
                if (lane == pos)                  { lv = v;   li = vj;  }
                else if (lane > pos && lane < 16) { lv = upv; li = upi; }
                tauV = __shfl_sync(FULLW, lv, 15);
                tauI = __shfl_sync(FULLW, li, 15);
            }
        }
    }
    outLv = lv; outLi = li;
}

// ---------------- KNN: branchless radius filter + warp bitonic selection ----------------
__global__ void __launch_bounds__(256) knn_filter(const float* __restrict__ coords) {
    __shared__ float4 tile[FTILE];                  // 16 KB
    __shared__ float          sd2[QPB][ROWW];       // 16.5 KB, row stride 129 (cf-free)
    __shared__ unsigned short sidx[QPB][ROWW];      // 8.25 KB
    __shared__ int            scnt[NSEG][QPB];      // 1 KB

    int tid = threadIdx.x;
    int b = blockIdx.y;
    int qbase = blockIdx.x * QPB;
    int ql = tid & (QPB-1);
    int seg = tid >> 5;          // == warp id; all lanes of a warp share seg
    int n = qbase + ql;
    const float* cb = coords + (size_t)b*NN*3;

    float qx = cb[n*3+0], qy = cb[n*3+1], qz = cb[n*3+2];
    float qsq = qx*qx + qy*qy + qz*qz;

    // per-query radius: target count ~40 from N(0,1) density, 2 corrections
    float rq = sqrtf(qsq);
    float R = cbrtf(0.018361f * expf(0.5f * qsq));
#pragma unroll
    for (int it = 0; it < 2; it++) {
        float re = fmaxf(rq - 0.5f*R, 0.f);
        R = cbrtf(0.018361f * expf(0.5f * re * re));
    }
    float tau = R*R - qsq;   // compare d2' = (|c|^2 - 2 q.c) < tau
    int cnt = 0;
    float* rowD = &sd2[ql][seg*CAP];
    unsigned short* rowI = &sidx[ql][seg*CAP];

    for (int t0 = 0; t0 < NN; t0 += FTILE) {
        __syncthreads();
        for (int u = tid; u < FTILE; u += 256) {
            int j = t0 + u;
            float x = cb[j*3+0], y = cb[j*3+1], z = cb[j*3+2];
            tile[u] = make_float4(-2.0f*x, -2.0f*y, -2.0f*z, x*x + y*y + z*z);
        }
        __syncthreads();

        int base = seg * (FTILE/NSEG);
#pragma unroll 4
        for (int e = 0; e < FTILE/NSEG; e++) {
            float4 c = tile[base + e];   // broadcast: all lanes same address
            float d2 = fmaf(qx, c.x, fmaf(qy, c.y, fmaf(qz, c.z, c.w)));
            if (d2 < tau) {
                int cc = min(cnt, CAP-1);   // clamped store: corruption only if flagged
                rowD[cc] = d2;
                rowI[cc] = (unsigned short)(t0 + base + e);
                cnt++;
            }
        }
    }
    scnt[seg][ql] = cnt;
    __syncthreads();

    // ---- selection: warp per query (8 warps x 4 queries), bitonic top-16 ----
    int warp = tid >> 5, lane = tid & 31;
    for (int it = 0; it < QPB/8; it++) {
        int q = warp*(QPB/8) + it;
        int qn = qbase + q;
        int cs[NSEG];
        bool over = false;
        int tot = 0;
#pragma unroll
        for (int k = 0; k < NSEG; k++) {
            cs[k] = scnt[k][q];
            over |= (cs[k] > CAP);
            tot += cs[k];
        }
        float fqx = cb[qn*3+0], fqy = cb[qn*3+1], fqz = cb[qn*3+2];

        float lv; int li;
        if (over || tot < KNN) {
            exact_knn_warp(cb, fqx, fqy, fqz, lane, lv, li);
        } else {
            // gather entry e -> (key, pay)
            float key; int pay;
            {
                int e = lane;
                key = 3.4e38f; pay = 0x7fffffff;
                int acc = 0;
#pragma unroll
                for (int k = 0; k < NSEG; k++) {
                    if (e >= acc && e < acc + cs[k]) {
                        key = sd2[q][k*CAP + (e - acc)];
                        pay = sidx[q][k*CAP + (e - acc)];
                    }
                    acc += cs[k];
                }
            }
            bitonic32(key, pay, lane);
            lv = (lane < 16) ? key : 3.4e38f;
            li = pay;
            for (int cb2 = 32; cb2 < tot; cb2 += 32) {
                int e = cb2 + lane;
                key = 3.4e38f; pay = 0x7fffffff;
                int acc = 0;
#pragma unroll
                for (int k = 0; k < NSEG; k++) {
                    if (e >= acc && e < acc + cs[k]) {
                        key = sd2[q][k*CAP + (e - acc)];
                        pay = sidx[q][k*CAP + (e - acc)];
                    }
                    acc += cs[k];
                }
                bitonic32(key, pay, lane);
                merge_chunk(key, pay, lv, li, lane);
            }
        }

        if (lane < KNN) {
            int j = li;
            float nx = cb[j*3+0], ny = cb[j*3+1], nz = cb[j*3+2];
            float dx = fqx-nx, dy = fqy-ny, dz = fqz-nz;
            g_nb[((size_t)b*NN + qn)*KNN + lane] =
                make_float4(nx, ny, nz, sqrtf(fmaf(dx, dx, fmaf(dy, dy, dz*dz))));
        }
    }
}

// ---------------- fused per-point pipeline (8 points per 256-thread block) ----------------
__device__ __forceinline__ float sigmoidf_(float x) { return 1.0f / (1.0f + expf(-x)); }

struct SArena {
    float4 nb[8][16];
    float  A[8][64];
    float  M[8][64];
    float  Hs[8][8];
    float  Sp[8][16];
    float  Fe8[32*8];
    float  F8[64*8];
    float  Out8[64*8];
    float  Part[4096];
};

template<int NOUT>
__device__ __forceinline__ void stage(
    SArena* s, float featv, float cx, float cy, float cz,
    const float* __restrict__ We, const float* __restrict__ Wn,
    const float* __restrict__ bl, const float* __restrict__ gl, const float* __restrict__ btl,
    const float* __restrict__ c1p, const float* __restrict__ c2p,
    const float* __restrict__ Ws,
    const float* __restrict__ Wmt, const float* __restrict__ bm,
    const float* __restrict__ gm,  const float* __restrict__ btm,
    int lane, int warp, int tid)
{
    const float bns = rsqrtf(1.0f + 1e-5f);
    float we0 = We[0*32+lane], we1 = We[1*32+lane], we2 = We[2*32+lane];
    float wn0 = Wn[0*32+lane], wn1 = Wn[1*32+lane], wn2 = Wn[2*32+lane], wn3 = Wn[3*32+lane];
    float scl = gl[lane]*bns, shb = btl[lane];
    float base = bl[lane];
    base = fmaf(we0, cx, fmaf(we1, cy, fmaf(we2, cz, base)));

    float e[16];
    float avg = 0.f, mx = -3.4e38f;
#pragma unroll
    for (int k = 0; k < 16; k++) {
        float4 nb = s->nb[warp][k];
        float v = fmaf(wn0, nb.x, fmaf(wn1, nb.y, fmaf(wn2, nb.z, fmaf(wn3, nb.w, base))));
        v = fmaxf(scl*v + shb, 0.f);
        e[k] = v;
        avg += v;
        mx = fmaxf(mx, v);
    }
    avg *= 0.0625f;
    s->A[warp][lane] = avg; s->A[warp][32 + lane] = featv;
    s->M[warp][lane] = mx;  s->M[warp][32 + lane] = featv;
    __syncwarp();

    {
        int j = lane & 7;
        int srcbit = (lane >> 3) & 1;
        int chalf = lane >> 4;
        const float* S = srcbit ? s->M[warp] : s->A[warp];
        float h = 0.f;
#pragma unroll
        for (int cq = 0; cq < 8; cq++) {
            int quad = chalf*8 + cq;
            float4 w4 = *reinterpret_cast<const float4*>(&c1p[(quad*8 + j)*4]);
            float4 a4 = *reinterpret_cast<const float4*>(&S[chalf*32 + cq*4]);
            h = fmaf(w4.x, a4.x, fmaf(w4.y, a4.y, fmaf(w4.z, a4.z, fmaf(w4.w, a4.w, h))));
        }
        h += __shfl_xor_sync(FULLW, h, 16);
        float h2 = fmaxf(h, 0.f);
        float hsv = h2 + __shfl_xor_sync(FULLW, h2, 8);
        if (lane < 8) s->Hs[warp][lane] = hsv;
    }
    __syncwarp();

    float4 hs0 = *reinterpret_cast<const float4*>(&s->Hs[warp][0]);
    float4 hs1 = *reinterpret_cast<const float4*>(&s->Hs[warp][4]);
    float a, b2;
    {
        float4 w0 = *reinterpret_cast<const float4*>(&c2p[lane*4]);
        float4 w1 = *reinterpret_cast<const float4*>(&c2p[(64 + lane)*4]);
        a = w0.x*hs0.x + w0.y*hs0.y + w0.z*hs0.z + w0.w*hs0.w
          + w1.x*hs1.x + w1.y*hs1.y + w1.z*hs1.z + w1.w*hs1.w;
        float4 v0 = *reinterpret_cast<const float4*>(&c2p[(32 + lane)*4]);
        float4 v1 = *reinterpret_cast<const float4*>(&c2p[(96 + lane)*4]);
        b2 = v0.x*hs0.x + v0.y*hs0.y + v0.z*hs0.z + v0.w*hs0.w
           + v1.x*hs1.x + v1.y*hs1.y + v1.z*hs1.z + v1.w*hs1.w;
    }
    float chA = sigmoidf_(a), chB = sigmoidf_(b2);
    float xf = featv * chB;

    float vs[16], vm[16];
#pragma unroll
    for (int k = 0; k < 16; k++) {
        float ek = e[k] * chA;
        e[k] = ek;
        vs[k] = ek + xf;
        vm[k] = fmaxf(ek, xf);
    }
    {
        bool up = (lane & 16);
#pragma unroll
        for (int i = 0; i < 8; i++) {
            float ss = up ? vs[i] : vs[i+8];
            float ks = up ? vs[i+8] : vs[i];
            vs[i] = ks + __shfl_xor_sync(FULLW, ss, 16);
            float sm2 = up ? vm[i] : vm[i+8];
            float km = up ? vm[i+8] : vm[i];
            vm[i] = fmaxf(km, __shfl_xor_sync(FULLW, sm2, 16));
        }
    }
    {
        bool up = (lane & 8);
#pragma unroll
        for (int i = 0; i < 4; i++) {
            float ss = up ? vs[i] : vs[i+4];
            float ks = up ? vs[i+4] : vs[i];
            vs[i] = ks + __shfl_xor_sync(FULLW, ss, 8);
            float sm2 = up ? vm[i] : vm[i+4];
            float km = up ? vm[i+4] : vm[i];
            vm[i] = fmaxf(km, __shfl_xor_sync(FULLW, sm2, 8));
        }
    }
    {
        bool up = (lane & 4);
#pragma unroll
        for (int i = 0; i < 2; i++) {
            float ss = up ? vs[i] : vs[i+2];
            float ks = up ? vs[i+2] : vs[i];
            vs[i] = ks + __shfl_xor_sync(FULLW, ss, 4);
            float sm2 = up ? vm[i] : vm[i+2];
            float km = up ? vm[i+2] : vm[i];
            vm[i] = fmaxf(km, __shfl_xor_sync(FULLW, sm2, 4));
        }
    }
    {
        bool up = (lane & 2);
        float ss = up ? vs[0] : vs[1];
        float ks = up ? vs[1] : vs[0];
        vs[0] = ks + __shfl_xor_sync(FULLW, ss, 2);
        float sm2 = up ? vm[0] : vm[1];
        float km = up ? vm[1] : vm[0];
        vm[0] = fmaxf(km, __shfl_xor_sync(FULLW, sm2, 2));
    }
    vs[0] += __shfl_xor_sync(FULLW, vs[0], 1);
    vm[0] = fmaxf(vm[0], __shfl_xor_sync(FULLW, vm[0], 1));

    float ws0 = Ws[0], ws1 = Ws[1];
    float sp = sigmoidf_(ws0 * vs[0] * (1.0f/64.0f) + ws1 * vm[0]);
    int kL = (((lane>>4)&1)<<3) | (((lane>>3)&1)<<2) | (((lane>>2)&1)<<1) | ((lane>>1)&1);
    if (!(lane & 1)) s->Sp[warp][kL] = sp;
    float sps = sp;
#pragma unroll
    for (int off = 16; off > 0; off >>= 1) sps += __shfl_xor_sync(FULLW, sps, off);
    sps *= 0.5f;
    __syncwarp();

    float fA = 0.f;
#pragma unroll
    for (int k = 0; k < 16; k++) fA = fmaf(e[k], s->Sp[warp][k], fA);

    s->F8[lane*8 + warp]        = fA;
    s->F8[(32 + lane)*8 + warp] = xf * sps;
    __syncthreads();

    constexpr int G = NOUT/32;
    {
        float acc[G][8];
#pragma unroll
        for (int g = 0; g < G; g++)
#pragma unroll
            for (int p = 0; p < 8; p++) acc[g][p] = 0.f;
        int jb = warp * 8;
#pragma unroll
        for (int jj = 0; jj < 8; jj++) {
            int j = jb + jj;
            float4 a0 = *reinterpret_cast<const float4*>(&s->F8[j*8]);
            float4 a1 = *reinterpret_cast<const float4*>(&s->F8[j*8+4]);
#pragma unroll
            for (int g = 0; g < G; g++) {
                float wv = Wmt[j*NOUT + g*32 + lane];
                acc[g][0] = fmaf(wv, a0.x, acc[g][0]);
                acc[g][1] = fmaf(wv, a0.y, acc[g][1]);
                acc[g][2] = fmaf(wv, a0.z, acc[g][2]);
                acc[g][3] = fmaf(wv, a0.w, acc[g][3]);
                acc[g][4] = fmaf(wv, a1.x, acc[g][4]);
                acc[g][5] = fmaf(wv, a1.y, acc[g][5]);
                acc[g][6] = fmaf(wv, a1.z, acc[g][6]);
                acc[g][7] = fmaf(wv, a1.w, acc[g][7]);
            }
        }
#pragma unroll
        for (int g = 0; g < G; g++) {
            int bidx = (warp*NOUT + g*32 + lane)*8;
            *reinterpret_cast<float4*>(&s->Part[bidx])   = make_float4(acc[g][0], acc[g][1], acc[g][2], acc[g][3]);
            *reinterpret_cast<float4*>(&s->Part[bidx+4]) = make_float4(acc[g][4], acc[g][5], acc[g][6], acc[g][7]);
        }
    }
    __syncthreads();

#pragma unroll
    for (int g = 0; g < G; g++) {
        int idx = g*256 + tid;
        int oc = idx >> 3, pp = idx & 7;
        float sum = 0.f;
#pragma unroll
        for (int w = 0; w < 8; w++) sum += s->Part[(w*NOUT + oc)*8 + pp];
        sum += bm[oc];
        s->Out8[idx] = fmaxf(gm[oc]*bns*sum + btm[oc], 0.f);
    }
    __syncthreads();
}

__global__ void __launch_bounds__(256) fused_kernel(
    const float* __restrict__ coords,
    const float* __restrict__ mlp1_b,
    const float* __restrict__ lse1_b, const float* __restrict__ lse1_g, const float* __restrict__ lse1_bt,
    const float* __restrict__ p1_Ws,  const float* __restrict__ p1_bm,  const float* __restrict__ p1_g, const float* __restrict__ p1_bt,
    const float* __restrict__ lse2_b, const float* __restrict__ lse2_g, const float* __restrict__ lse2_bt,
    const float* __restrict__ p2_Ws,  const float* __restrict__ p2_bm,  const float* __restrict__ p2_g, const float* __restrict__ p2_bt,
    const float* __restrict__ mlp2_b,
    const float* __restrict__ sc_b, const float* __restrict__ sc_g, const float* __restrict__ sc_bt,
    float* __restrict__ out)
{
    __shared__ SArena s;

    int tid = threadIdx.x;
    int warp = tid >> 5, lane = tid & 31;
    int p = blockIdx.x * 8 + warp;
    int b = p >> 13, n = p & (NN - 1);

    s.Fe8[lane*8 + warp] = g_feat_t[p*CIN + lane];

    const float* cb = coords + ((size_t)b*NN + n)*3;
    float cx = cb[0], cy = cb[1], cz = cb[2];
    if (lane < 16) {
        s.nb[warp][lane] = g_nb[(size_t)p*KNN + lane];
    }
    __syncwarp();

    float x1;
    {
        float acc = mlp1_b[lane];
#pragma unroll
        for (int d = 0; d < 32; d++) acc = fmaf(g_mlp1Wt[d*32 + lane], s.Fe8[d*8 + warp], acc);
        x1 = acc >= 0.f ? acc : 0.2f*acc;
    }

    stage<32>(&s, x1, cx, cy, cz, g_lse1We, g_lse1Wn, lse1_b, lse1_g, lse1_bt,
              g_p1c1p, g_p1c2p, p1_Ws, g_p1wmt, p1_bm, p1_g, p1_bt, lane, warp, tid);
    float o1 = s.Out8[lane*8 + warp];

    stage<64>(&s, o1, cx, cy, cz, g_lse2We, g_lse2Wn, lse2_b, lse2_g, lse2_bt,
              g_p2c1p, g_p2c2p, p2_Ws, g_p2wmt, p2_bm, p2_g, p2_bt, lane, warp, tid);

    {
        int slice = tid >> 6;
        int oc0 = (tid & 63) * 2;
        float acc0[8], acc1[8];
#pragma unroll
        for (int q = 0; q < 8; q++) { acc0[q] = 0.f; acc1[q] = 0.f; }
#pragma unroll
        for (int jj = 0; jj < 16; jj++) {
            int j = slice*16 + jj;
            float2 w2 = *reinterpret_cast<const float2*>(&g_mlp2t[j*128 + oc0]);
            float4 a0 = *reinterpret_cast<const float4*>(&s.Out8[j*8]);
            float4 a1 = *reinterpret_cast<const float4*>(&s.Out8[j*8+4]);
            acc0[0] = fmaf(w2.x, a0.x, acc0[0]); acc1[0] = fmaf(w2.y, a0.x, acc1[0]);
            acc0[1] = fmaf(w2.x, a0.y, acc0[1]); acc1[1] = fmaf(w2.y, a0.y, acc1[1]);
            acc0[2] = fmaf(w2.x, a0.z, acc0[2]); acc1[2] = fmaf(w2.y, a0.z, acc1[2]);
            acc0[3] = fmaf(w2.x, a0.w, acc0[3]); acc1[3] = fmaf(w2.y, a0.w, acc1[3]);
            acc0[4] = fmaf(w2.x, a1.x, acc0[4]); acc1[4] = fmaf(w2.y, a1.x, acc1[4]);
            acc0[5] = fmaf(w2.x, a1.y, acc0[5]); acc1[5] = fmaf(w2.y, a1.y, acc1[5]);
            acc0[6] = fmaf(w2.x, a1.z, acc0[6]); acc1[6] = fmaf(w2.y, a1.z, acc1[6]);
            acc0[7] = fmaf(w2.x, a1.w, acc0[7]); acc1[7] = fmaf(w2.y, a1.w, acc1[7]);
        }
#pragma unroll
        for (int dd = 0; dd < 8; dd++) {
            int d = slice*8 + dd;
            float2 w2 = *reinterpret_cast<const float2*>(&g_scWt[d*128 + oc0]);
            float4 f0 = *reinterpret_cast<const float4*>(&s.Fe8[d*8]);
            float4 f1 = *reinterpret_cast<const float4*>(&s.Fe8[d*8+4]);
            acc0[0] = fmaf(w2.x, f0.x, acc0[0]); acc1[0] = fmaf(w2.y, f0.x, acc1[0]);
            acc0[1] = fmaf(w2.x, f0.y, acc0[1]); acc1[1] = fmaf(w2.y, f0.y, acc1[1]);
            acc0[2] = fmaf(w2.x, f0.z, acc0[2]); acc1[2] = fmaf(w2.y, f0.z, acc1[2]);
            acc0[3] = fmaf(w2.x, f0.w, acc0[3]); acc1[3] = fmaf(w2.y, f0.w, acc1[3]);
            acc0[4] = fmaf(w2.x, f1.x, acc0[4]); acc1[4] = fmaf(w2.y, f1.x, acc1[4]);
            acc0[5] = fmaf(w2.x, f1.y, acc0[5]); acc1[5] = fmaf(w2.y, f1.y, acc1[5]);
            acc0[6] = fmaf(w2.x, f1.z, acc0[6]); acc1[6] = fmaf(w2.y, f1.z, acc1[6]);
            acc0[7] = fmaf(w2.x, f1.w, acc0[7]); acc1[7] = fmaf(w2.y, f1.w, acc1[7]);
        }
        int b0 = (slice*128 + oc0)*8;
        *reinterpret_cast<float4*>(&s.Part[b0])     = make_float4(acc0[0], acc0[1], acc0[2], acc0[3]);
        *reinterpret_cast<float4*>(&s.Part[b0+4])   = make_float4(acc0[4], acc0[5], acc0[6], acc0[7]);
        *reinterpret_cast<float4*>(&s.Part[b0+8])   = make_float4(acc1[0], acc1[1], acc1[2], acc1[3]);
        *reinterpret_cast<float4*>(&s.Part[b0+12])  = make_float4(acc1[4], acc1[5], acc1[6], acc1[7]);
    }
    __syncthreads();

    {
        const float bns = rsqrtf(1.0f + 1e-5f);
        int oc = tid & 127;
        int ph = tid >> 7;
        float4 v = make_float4(0.f, 0.f, 0.f, 0.f);
#pragma unroll
        for (int sl = 0; sl < 4; sl++) {
            float4 t = *reinterpret_cast<const float4*>(&s.Part[(sl*128 + oc)*8 + ph*4]);
            v.x += t.x; v.y += t.y; v.z += t.z; v.w += t.w;
        }
        float basev = mlp2_b[oc] + sc_g[oc]*bns*sc_b[oc] + sc_bt[oc];
        v.x += basev; v.y += basev; v.z += basev; v.w += basev;
        v.x = v.x >= 0.f ? v.x : 0.01f*v.x;
        v.y = v.y >= 0.f ? v.y : 0.01f*v.y;
        v.z = v.z >= 0.f ? v.z : 0.01f*v.z;
        v.w = v.w >= 0.f ? v.w : 0.01f*v.w;

        int p0 = blockIdx.x * 8;
        int b0 = p0 >> 13, n0 = p0 & (NN - 1);
        *reinterpret_cast<float4*>(&out[((size_t)(b0*128 + oc))*NN + n0 + ph*4]) = v;
    }
}

// ---------------- launch ----------------
extern "C" void kernel_launch(void* const* d_in, const int* in_sizes, int n_in,
                              void* d_out, int out_size) {
    const float* coords   = (const float*)d_in[0];
    const float* features = (const float*)d_in[1];
    const float* mlp1_W = (const float*)d_in[2];
    const float* mlp1_b = (const float*)d_in[3];
    const float* lse1_W = (const float*)d_in[4];
    const float* lse1_b = (const float*)d_in[5];
    const float* lse1_g = (const float*)d_in[6];
    const float* lse1_bt = (const float*)d_in[7];
    const float* p1_Wc1 = (const float*)d_in[8];
    const float* p1_Wc2 = (const float*)d_in[9];
    const float* p1_Ws  = (const float*)d_in[10];
    const float* p1_Wm  = (const float*)d_in[11];
    const float* p1_bm  = (const float*)d_in[12];
    const float* p1_g   = (const float*)d_in[13];
    const float* p1_bt  = (const float*)d_in[14];
    const float* lse2_W = (const float*)d_in[15];
    const float* lse2_b = (const float*)d_in[16];
    const float* lse2_g = (const float*)d_in[17];
    const float* lse2_bt = (const float*)d_in[18];
    const float* p2_Wc1 = (const float*)d_in[19];
    const float* p2_Wc2 = (const float*)d_in[20];
    const float* p2_Ws  = (const float*)d_in[21];
    const float* p2_Wm  = (const float*)d_in[22];
    const float* p2_bm  = (const float*)d_in[23];
    const float* p2_g   = (const float*)d_in[24];
    const float* p2_bt  = (const float*)d_in[25];
    const float* mlp2_W = (const float*)d_in[26];
    const float* mlp2_b = (const float*)d_in[27];
    const float* sc_W   = (const float*)d_in[28];
    const float* sc_b   = (const float*)d_in[29];
    const float* sc_g   = (const float*)d_in[30];
    const float* sc_bt  = (const float*)d_in[31];
    float* out = (float*)d_out;

    int prep_blocks = 11 + (BB*NN*CIN + 255)/256;
    prep_all<<<prep_blocks, 256>>>(mlp1_W, lse1_W, lse2_W, p1_Wc1, p1_Wc2, p1_Wm,
                                   p2_Wc1, p2_Wc2, p2_Wm, mlp2_W, sc_W, sc_g, features);
    knn_filter<<<dim3(NN/QPB, BB), 256>>>(coords);
    fused_kernel<<<(BB*NN)/8, 256>>>(coords, mlp1_b, lse1_b, lse1_g, lse1_bt,
                                     p1_Ws, p1_bm, p1_g, p1_bt,
                                     lse2_b, lse2_g, lse2_bt,
                                     p2_Ws, p2_bm, p2_g, p2_bt,
                                     mlp2_b, sc_b, sc_g, sc_bt, out);
}

// round 15
// speedup vs baseline: 2.5924x; 1.0621x over previous
#include <cuda_runtime.h>
#include <math.h>

#define BB 2
#define NN 8192
#define KNN 16
#define CIN 32
#define FULLW 0xffffffffu

// knn filter config
#define QPB 32      // queries per block
#define NSEG 8      // candidate segments (one warp of lanes per seg)
#define CAP 20      // buffer capacity per (query, segment)
#define ROWW (NSEG*CAP + 1)   // 161: padded row -> conflict-free
#define FTILE 512   // candidates staged per tile

// ---------------- scratch ----------------
__device__ float  g_feat_t[BB*NN*CIN];
__device__ float4 g_nb[BB*NN*KNN]; // (nx, ny, nz, dist) per point per k, ascending
// weights, repacked by prep
__device__ float g_mlp1Wt[32*32];
__device__ float g_lse1We[3*32];
__device__ float g_lse1Wn[4*32];
__device__ float g_lse2We[3*32];
__device__ float g_lse2Wn[4*32];
__device__ float g_p1c1p[512];
__device__ float g_p1c2p[512];
__device__ float g_p1wmt[64*32];
__device__ float g_p2c1p[512];
__device__ float g_p2c2p[512];
__device__ float g_p2wmt[64*64];
__device__ float g_mlp2t[64*128];
__device__ float g_scWt[32*128];   // pre-scaled by sc_g*bns

// ---------------- prep: weights + tiled feat transpose ----------------
__global__ void prep_all(
    const float* __restrict__ mlp1_W,
    const float* __restrict__ lse1_W,
    const float* __restrict__ lse2_W,
    const float* __restrict__ p1c1, const float* __restrict__ p1c2, const float* __restrict__ p1wm,
    const float* __restrict__ p2c1, const float* __restrict__ p2c2, const float* __restrict__ p2wm,
    const float* __restrict__ mlp2_W, const float* __restrict__ sc_W,
    const float* __restrict__ sc_g, const float* __restrict__ features)
{
    const float bns = rsqrtf(1.0f + 1e-5f);
    int t = threadIdx.x;
    int bid = blockIdx.x;
    if (bid < 11) {
        switch (bid) {
            case 0:
                for (int i = t; i < 32*32; i += 256) g_mlp1Wt[(i%32)*32 + (i/32)] = mlp1_W[i];
                break;
            case 1:
                if (t < 32) {
                    for (int d = 0; d < 3; d++) {
                        g_lse1We[d*32+t] = lse1_W[t*10+d]   + lse1_W[t*10+6+d];
                        g_lse1Wn[d*32+t] = lse1_W[t*10+3+d] - lse1_W[t*10+6+d];
                    }
                    g_lse1Wn[3*32+t] = lse1_W[t*10+9];
                }
                break;
            case 2:
                if (t < 32) {
                    for (int d = 0; d < 3; d++) {
                        g_lse2We[d*32+t] = lse2_W[t*10+d]   + lse2_W[t*10+6+d];
                        g_lse2Wn[d*32+t] = lse2_W[t*10+3+d] - lse2_W[t*10+6+d];
                    }
                    g_lse2Wn[3*32+t] = lse2_W[t*10+9];
                }
                break;
            case 3:
                for (int i = t; i < 512; i += 256) {
                    int j = i / 64, c = i % 64;
                    g_p1c1p[((c>>2)*8 + j)*4 + (c&3)] = p1c1[i];
                }
                break;
            case 4:
                for (int i = t; i < 512; i += 256) {
                    int r = i / 8, c = i % 8;
                    g_p1c2p[((c>>2)*64 + r)*4 + (c&3)] = p1c2[i];
                }
                break;
            case 5:
                for (int i = t; i < 32*64; i += 256) g_p1wmt[(i%64)*32 + (i/64)] = p1wm[i];
                break;
            case 6:
                for (int i = t; i < 512; i += 256) {
                    int j = i / 64, c = i % 64;
                    g_p2c1p[((c>>2)*8 + j)*4 + (c&3)] = p2c1[i];
                }
                break;
            case 7:
                for (int i = t; i < 512; i += 256) {
                    int r = i / 8, c = i % 8;
                    g_p2c2p[((c>>2)*64 + r)*4 + (c&3)] = p2c2[i];
                }
                break;
            case 8:
                for (int i = t; i < 64*64; i += 256) g_p2wmt[(i%64)*64 + (i/64)] = p2wm[i];
                break;
            case 9:
                for (int i = t; i < 128*64; i += 256) g_mlp2t[(i%64)*128 + (i/64)] = mlp2_W[i];
                break;
            default:
                for (int i = t; i < 128*32; i += 256) {
                    int oc = i / 32, d = i % 32;
                    g_scWt[d*128 + oc] = sc_W[i] * sc_g[oc] * bns;
                }
                break;
        }
        return;
    }
    // tiled feat transpose: 32 n x 32 c per block, both sides coalesced
    {
        __shared__ float tile[32][33];
        int tb = bid - 11;                 // 0 .. BB*NN/32 - 1
        int b = tb / (NN/32);
        int n0 = (tb % (NN/32)) * 32;
        int w = t >> 5, l = t & 31;
        for (int cc = w; cc < 32; cc += 8)
            tile[cc][l] = features[((size_t)b*CIN + cc)*NN + n0 + l];
        __syncthreads();
        for (int nn = w; nn < 32; nn += 8)
            g_feat_t[((size_t)b*NN + n0 + nn)*CIN + l] = tile[l][nn];
    }
}

// ---------------- bitonic helpers ----------------
__device__ __forceinline__ void bitonic32(float& key, int& pay, int lane) {
#pragma unroll
    for (int k = 2; k <= 32; k <<= 1) {
#pragma unroll
        for (int j = k >> 1; j > 0; j >>= 1) {
            float ok = __shfl_xor_sync(FULLW, key, j);
            int   op = __shfl_xor_sync(FULLW, pay, j);
            bool takeMin = (((lane & j) == 0) == ((lane & k) == 0));
            bool less = (ok < key) || (ok == key && op < pay);
            if (takeMin ? less : !less) { key = ok; pay = op; }
        }
    }
}

__device__ __forceinline__ void merge_chunk(
    float key, int pay, float& lv, int& li, int lane)
{
    float ck = __shfl_xor_sync(FULLW, key, 31);
    int   cp = __shfl_xor_sync(FULLW, pay, 31);
    float v  = (lane < 16) ? lv : ck;
    int   vp = (lane < 16) ? li : cp;
#pragma unroll
    for (int j = 16; j > 0; j >>= 1) {
        float ov  = __shfl_xor_sync(FULLW, v, j);
        int   ovp = __shfl_xor_sync(FULLW, vp, j);
        bool takeMin = ((lane & j) == 0);
        bool less = (ov < v) || (ov == v && ovp < vp);
        if (takeMin ? less : !less) { v = ov; vp = ovp; }
    }
    lv = v; li = vp;
}

// warp-cooperative exact scan (fallback; proven R9-R13 machinery)
__device__ void exact_knn_warp(
    const float* __restrict__ cb, float qx, float qy, float qz,
    int lane, float& outLv, int& outLi)
{
    float lv = 3.4e38f; int li = 0x7fffffff;
    float tauV = 3.4e38f; int tauI = 0x7fffffff;
    bool seeded = false;
    for (int f = 0; f < NN; f += 32) {
        int j = f + lane;
        float x = cb[3*j], y = cb[3*j+1], z = cb[3*j+2];
        float dx = qx-x, dy = qy-y, dz = qz-z;
        float d2 = fmaf(dx, dx, fmaf(dy, dy, dz*dz));
        if (!seeded) {
            float key = d2; int pay = j;
            bitonic32(key, pay, lane);
            lv = (lane < 16) ? key : 3.4e38f;
            li = pay;
            tauV = __shfl_sync(FULLW, key, 15);
            tauI = __shfl_sync(FULLW, pay, 15);
            seeded = true;
            continue;
        }
        unsigned m = __ballot_sync(FULLW, (d2 < tauV) || (d2 == tauV && j < tauI));
        while (m) {
            int src = __ffs(m) - 1;
            m &= m - 1;
            float v  = __shfl_sync(FULLW, d2, src);
            int   vj = __shfl_sync(FULLW, j, src);
            if ((v < tauV) || (v == tauV && vj < tauI)) {
                unsigned le = __ballot_sync(FULLW,
                    (lane < 16) && ((lv < v) || (lv == v && li < vj)));
                int pos = __popc(le);
                float upv = __shfl_up_sync(FULLW, lv, 1);
                int   upi = __shfl_up_sync(FULLW, li, 1);
                if (lane == pos)                  { lv = v;   li = vj;  }
                else if (lane > pos && lane < 16) { lv = upv; li = upi; }
                tauV = __shfl_sync(FULLW, lv, 15);
                tauI = __shfl_sync(FULLW, li, 15);
            }
        }
    }
    outLv = lv; outLi = li;
}

// ---------------- KNN: branchless radius filter + warp bitonic selection ----------------
__global__ void __launch_bounds__(256) knn_filter(const float* __restrict__ coords) {
    __shared__ float4 tile[FTILE];                  // 8 KB
    __shared__ float          sd2[QPB][ROWW];       // 20.6 KB (161 stride, cf-free)
    __shared__ unsigned short sidx[QPB][ROWW];      // 10.3 KB
    __shared__ int            scnt[NSEG][QPB];      // 1 KB

    int tid = threadIdx.x;
    int b = blockIdx.y;
    int qbase = blockIdx.x * QPB;
    int ql = tid & (QPB-1);
    int seg = tid >> 5;
    int n = qbase + ql;
    const float* cb = coords + (size_t)b*NN*3;

    float qx = cb[n*3+0], qy = cb[n*3+1], qz = cb[n*3+2];
    float qsq = qx*qx + qy*qy + qz*qz;

    // radius for target count ~56 using density at q (3.5x margin to K=16); clamp R<=1
    float R = cbrtf(0.02571f * expf(0.5f * qsq));
    R = fminf(R, 1.0f);
    float tau = R*R - qsq;   // compare d2' = (|c|^2 - 2 q.c) < tau
    int cnt = 0;
    float* rowD = &sd2[ql][seg*CAP];
    unsigned short* rowI = &sidx[ql][seg*CAP];

    for (int t0 = 0; t0 < NN; t0 += FTILE) {
        __syncthreads();
        for (int u = tid; u < FTILE; u += 256) {
            int j = t0 + u;
            float x = cb[j*3+0], y = cb[j*3+1], z = cb[j*3+2];
            tile[u] = make_float4(-2.0f*x, -2.0f*y, -2.0f*z, x*x + y*y + z*z);
        }
        __syncthreads();

        int base = seg * (FTILE/NSEG);
#pragma unroll 4
        for (int e = 0; e < FTILE/NSEG; e++) {
            float4 c = tile[base + e];   // broadcast
            float d2 = fmaf(qx, c.x, fmaf(qy, c.y, fmaf(qz, c.z, c.w)));
            if (d2 < tau) {
                int cc = min(cnt, CAP-1);   // clamped; overwrite only if flagged
                rowD[cc] = d2;
                rowI[cc] = (unsigned short)(t0 + base + e);
                cnt++;
            }
        }
    }
    scnt[seg][ql] = cnt;
    __syncthreads();

    // ---- selection: warp per query, bitonic top-16 ----
    int warp = tid >> 5, lane = tid & 31;
    for (int it = 0; it < QPB/8; it++) {
        int q = warp*(QPB/8) + it;
        int qn = qbase + q;
        int cs[NSEG];
        bool over = false;
        int tot = 0;
#pragma unroll
        for (int k = 0; k < NSEG; k++) {
            cs[k] = scnt[k][q];
            over |= (cs[k] > CAP);
            tot += cs[k];
        }
        float fqx = cb[qn*3+0], fqy = cb[qn*3+1], fqz = cb[qn*3+2];

        float lv; int li;
        if (over || tot < KNN) {
            exact_knn_warp(cb, fqx, fqy, fqz, lane, lv, li);
        } else {
            float key; int pay;
            {
                int e = lane;
                key = 3.4e38f; pay = 0x7fffffff;
                int acc = 0;
#pragma unroll
                for (int k = 0; k < NSEG; k++) {
                    if (e >= acc && e < acc + cs[k]) {
                        key = sd2[q][k*CAP + (e - acc)];
                        pay = sidx[q][k*CAP + (e - acc)];
                    }
                    acc += cs[k];
                }
            }
            bitonic32(key, pay, lane);
            lv = (lane < 16) ? key : 3.4e38f;
            li = pay;
            for (int cb2 = 32; cb2 < tot; cb2 += 32) {
                int e = cb2 + lane;
                key = 3.4e38f; pay = 0x7fffffff;
                int acc = 0;
#pragma unroll
                for (int k = 0; k < NSEG; k++) {
                    if (e >= acc && e < acc + cs[k]) {
                        key = sd2[q][k*CAP + (e - acc)];
                        pay = sidx[q][k*CAP + (e - acc)];
                    }
                    acc += cs[k];
                }
                bitonic32(key, pay, lane);
                merge_chunk(key, pay, lv, li, lane);
            }
        }

        if (lane < KNN) {
            int j = li;
            float nx = cb[j*3+0], ny = cb[j*3+1], nz = cb[j*3+2];
            float dx = fqx-nx, dy = fqy-ny, dz = fqz-nz;
            g_nb[((size_t)b*NN + qn)*KNN + lane] =
                make_float4(nx, ny, nz, sqrtf(fmaf(dx, dx, fmaf(dy, dy, dz*dz))));
        }
    }
}

// ---------------- fused per-point pipeline (8 points per 256-thread block) ----------------
__device__ __forceinline__ float sigmoidf_(float x) { return 1.0f / (1.0f + expf(-x)); }

struct SArena {
    float4 nb[8][16];
    float  A[8][64];
    float  M[8][64];
    float  Hs[8][8];
    float  Sp[8][16];
    float  Fe8[32*8];
    float  F8[64*8];
    float  Out8[64*8];
    float  Part[4096];
};

template<int NOUT>
__device__ __forceinline__ void stage(
    SArena* s, float featv, float cx, float cy, float cz,
    const float* __restrict__ We, const float* __restrict__ Wn,
    const float* __restrict__ bl, const float* __restrict__ gl, const float* __restrict__ btl,
    const float* __restrict__ c1p, const float* __restrict__ c2p,
    const float* __restrict__ Ws,
    const float* __restrict__ Wmt, const float* __restrict__ bm,
    const float* __restrict__ gm,  const float* __restrict__ btm,
    int lane, int warp, int tid)
{
    const float bns = rsqrtf(1.0f + 1e-5f);
    float we0 = We[0*32+lane], we1 = We[1*32+lane], we2 = We[2*32+lane];
    float wn0 = Wn[0*32+lane], wn1 = Wn[1*32+lane], wn2 = Wn[2*32+lane], wn3 = Wn[3*32+lane];
    float scl = gl[lane]*bns, shb = btl[lane];
    float base = bl[lane];
    base = fmaf(we0, cx, fmaf(we1, cy, fmaf(we2, cz, base)));

    float e[16];
    float avg = 0.f, mx = -3.4e38f;
#pragma unroll
    for (int k = 0; k < 16; k++) {
        float4 nb = s->nb[warp][k];
        float v = fmaf(wn0, nb.x, fmaf(wn1, nb.y, fmaf(wn2, nb.z, fmaf(wn3, nb.w, base))));
        v = fmaxf(scl*v + shb, 0.f);
        e[k] = v;
        avg += v;
        mx = fmaxf(mx, v);
    }
    avg *= 0.0625f;
    s->A[warp][lane] = avg; s->A[warp][32 + lane] = featv;
    s->M[warp][lane] = mx;  s->M[warp][32 + lane] = featv;
    __syncwarp();

    {
        int j = lane & 7;
        int srcbit = (lane >> 3) & 1;
        int chalf = lane >> 4;
        const float* S = srcbit ? s->M[warp] : s->A[warp];
        float h = 0.f;
#pragma unroll
        for (int cq = 0; cq < 8; cq++) {
            int quad = chalf*8 + cq;
            float4 w4 = *reinterpret_cast<const float4*>(&c1p[(quad*8 + j)*4]);
            float4 a4 = *reinterpret_cast<const float4*>(&S[chalf*32 + cq*4]);
            h = fmaf(w4.x, a4.x, fmaf(w4.y, a4.y, fmaf(w4.z, a4.z, fmaf(w4.w, a4.w, h))));
        }
        h += __shfl_xor_sync(FULLW, h, 16);
        float h2 = fmaxf(h, 0.f);
        float hsv = h2 + __shfl_xor_sync(FULLW, h2, 8);
        if (lane < 8) s->Hs[warp][lane] = hsv;
    }
    __syncwarp();

    float4 hs0 = *reinterpret_cast<const float4*>(&s->Hs[warp][0]);
    float4 hs1 = *reinterpret_cast<const float4*>(&s->Hs[warp][4]);
    float a, b2;
    {
        float4 w0 = *reinterpret_cast<const float4*>(&c2p[lane*4]);
        float4 w1 = *reinterpret_cast<const float4*>(&c2p[(64 + lane)*4]);
        a = w0.x*hs0.x + w0.y*hs0.y + w0.z*hs0.z + w0.w*hs0.w
          + w1.x*hs1.x + w1.y*hs1.y + w1.z*hs1.z + w1.w*hs1.w;
        float4 v0 = *reinterpret_cast<const float4*>(&c2p[(32 + lane)*4]);
        float4 v1 = *reinterpret_cast<const float4*>(&c2p[(96 + lane)*4]);
        b2 = v0.x*hs0.x + v0.y*hs0.y + v0.z*hs0.z + v0.w*hs0.w
           + v1.x*hs1.x + v1.y*hs1.y + v1.z*hs1.z + v1.w*hs1.w;
    }
    float chA = sigmoidf_(a), chB = sigmoidf_(b2);
    float xf = featv * chB;

    float vs[16], vm[16];
#pragma unroll
    for (int k = 0; k < 16; k++) {
        float ek = e[k] * chA;
        e[k] = ek;
        vs[k] = ek + xf;
        vm[k] = fmaxf(ek, xf);
    }
    {
        bool up = (lane & 16);
#pragma unroll
        for (int i = 0; i < 8; i++) {
            float ss = up ? vs[i] : vs[i+8];
            float ks = up ? vs[i+8] : vs[i];
            vs[i] = ks + __shfl_xor_sync(FULLW, ss, 16);
            float sm2 = up ? vm[i] : vm[i+8];
            float km = up ? vm[i+8] : vm[i];
            vm[i] = fmaxf(km, __shfl_xor_sync(FULLW, sm2, 16));
        }
    }
    {
        bool up = (lane & 8);
#pragma unroll
        for (int i = 0; i < 4; i++) {
            float ss = up ? vs[i] : vs[i+4];
            float ks = up ? vs[i+4] : vs[i];
            vs[i] = ks + __shfl_xor_sync(FULLW, ss, 8);
            float sm2 = up ? vm[i] : vm[i+4];
            float km = up ? vm[i+4] : vm[i];
            vm[i] = fmaxf(km, __shfl_xor_sync(FULLW, sm2, 8));
        }
    }
    {
        bool up = (lane & 4);
#pragma unroll
        for (int i = 0; i < 2; i++) {
            float ss = up ? vs[i] : vs[i+2];
            float ks = up ? vs[i+2] : vs[i];
            vs[i] = ks + __shfl_xor_sync(FULLW, ss, 4);
            float sm2 = up ? vm[i] : vm[i+2];
            float km = up ? vm[i+2] : vm[i];
            vm[i] = fmaxf(km, __shfl_xor_sync(FULLW, sm2, 4));
        }
    }
    {
        bool up = (lane & 2);
        float ss = up ? vs[0] : vs[1];
        float ks = up ? vs[1] : vs[0];
        vs[0] = ks + __shfl_xor_sync(FULLW, ss, 2);
        float sm2 = up ? vm[0] : vm[1];
        float km = up ? vm[1] : vm[0];
        vm[0] = fmaxf(km, __shfl_xor_sync(FULLW, sm2, 2));
    }
    vs[0] += __shfl_xor_sync(FULLW, vs[0], 1);
    vm[0] = fmaxf(vm[0], __shfl_xor_sync(FULLW, vm[0], 1));

    float ws0 = Ws[0], ws1 = Ws[1];
    float sp = sigmoidf_(ws0 * vs[0] * (1.0f/64.0f) + ws1 * vm[0]);
    int kL = (((lane>>4)&1)<<3) | (((lane>>3)&1)<<2) | (((lane>>2)&1)<<1) | ((lane>>1)&1);
    if (!(lane & 1)) s->Sp[warp][kL] = sp;
    float sps = sp;
#pragma unroll
    for (int off = 16; off > 0; off >>= 1) sps += __shfl_xor_sync(FULLW, sps, off);
    sps *= 0.5f;
    __syncwarp();

    float fA = 0.f;
#pragma unroll
    for (int k = 0; k < 16; k++) fA = fmaf(e[k], s->Sp[warp][k], fA);

    s->F8[lane*8 + warp]        = fA;
    s->F8[(32 + lane)*8 + warp] = xf * sps;
    __syncthreads();

    constexpr int G = NOUT/32;
    {
        float acc[G][8];
#pragma unroll
        for (int g = 0; g < G; g++)
#pragma unroll
            for (int p = 0; p < 8; p++) acc[g][p] = 0.f;
        int jb = warp * 8;
#pragma unroll
        for (int jj = 0; jj < 8; jj++) {
            int j = jb + jj;
            float4 a0 = *reinterpret_cast<const float4*>(&s->F8[j*8]);
            float4 a1 = *reinterpret_cast<const float4*>(&s->F8[j*8+4]);
#pragma unroll
            for (int g = 0; g < G; g++) {
                float wv = Wmt[j*NOUT + g*32 + lane];
                acc[g][0] = fmaf(wv, a0.x, acc[g][0]);
                acc[g][1] = fmaf(wv, a0.y, acc[g][1]);
                acc[g][2] = fmaf(wv, a0.z, acc[g][2]);
                acc[g][3] = fmaf(wv, a0.w, acc[g][3]);
                acc[g][4] = fmaf(wv, a1.x, acc[g][4]);
                acc[g][5] = fmaf(wv, a1.y, acc[g][5]);
                acc[g][6] = fmaf(wv, a1.z, acc[g][6]);
                acc[g][7] = fmaf(wv, a1.w, acc[g][7]);
            }
        }
#pragma unroll
        for (int g = 0; g < G; g++) {
            int bidx = (warp*NOUT + g*32 + lane)*8;
            *reinterpret_cast<float4*>(&s->Part[bidx])   = make_float4(acc[g][0], acc[g][1], acc[g][2], acc[g][3]);
            *reinterpret_cast<float4*>(&s->Part[bidx+4]) = make_float4(acc[g][4], acc[g][5], acc[g][6], acc[g][7]);
        }
    }
    __syncthreads();

#pragma unroll
    for (int g = 0; g < G; g++) {
        int idx = g*256 + tid;
        int oc = idx >> 3, pp = idx & 7;
        float sum = 0.f;
#pragma unroll
        for (int w = 0; w < 8; w++) sum += s->Part[(w*NOUT + oc)*8 + pp];
        sum += bm[oc];
        s->Out8[idx] = fmaxf(gm[oc]*bns*sum + btm[oc], 0.f);
    }
    __syncthreads();
}

__global__ void __launch_bounds__(256) fused_kernel(
    const float* __restrict__ coords,
    const float* __restrict__ mlp1_b,
    const float* __restrict__ lse1_b, const float* __restrict__ lse1_g, const float* __restrict__ lse1_bt,
    const float* __restrict__ p1_Ws,  const float* __restrict__ p1_bm,  const float* __restrict__ p1_g, const float* __restrict__ p1_bt,
    const float* __restrict__ lse2_b, const float* __restrict__ lse2_g, const float* __restrict__ lse2_bt,
    const float* __restrict__ p2_Ws,  const float* __restrict__ p2_bm,  const float* __restrict__ p2_g, const float* __restrict__ p2_bt,
    const float* __restrict__ mlp2_b,
    const float* __restrict__ sc_b, const float* __restrict__ sc_g, const float* __restrict__ sc_bt,
    float* __restrict__ out)
{
    __shared__ SArena s;

    int tid = threadIdx.x;
    int warp = tid >> 5, lane = tid & 31;
    int p = blockIdx.x * 8 + warp;
    int b = p >> 13, n = p & (NN - 1);

    s.Fe8[lane*8 + warp] = g_feat_t[p*CIN + lane];

    const float* cb = coords + ((size_t)b*NN + n)*3;
    float cx = cb[0], cy = cb[1], cz = cb[2];
    if (lane < 16) {
        s.nb[warp][lane] = g_nb[(size_t)p*KNN + lane];
    }
    __syncwarp();

    float x1;
    {
        float acc = mlp1_b[lane];
#pragma unroll
        for (int d = 0; d < 32; d++) acc = fmaf(g_mlp1Wt[d*32 + lane], s.Fe8[d*8 + warp], acc);
        x1 = acc >= 0.f ? acc : 0.2f*acc;
    }

    stage<32>(&s, x1, cx, cy, cz, g_lse1We, g_lse1Wn, lse1_b, lse1_g, lse1_bt,
              g_p1c1p, g_p1c2p, p1_Ws, g_p1wmt, p1_bm, p1_g, p1_bt, lane, warp, tid);
    float o1 = s.Out8[lane*8 + warp];

    stage<64>(&s, o1, cx, cy, cz, g_lse2We, g_lse2Wn, lse2_b, lse2_g, lse2_bt,
              g_p2c1p, g_p2c2p, p2_Ws, g_p2wmt, p2_bm, p2_g, p2_bt, lane, warp, tid);

    {
        int slice = tid >> 6;
        int oc0 = (tid & 63) * 2;
        float acc0[8], acc1[8];
#pragma unroll
        for (int q = 0; q < 8; q++) { acc0[q] = 0.f; acc1[q] = 0.f; }
#pragma unroll
        for (int jj = 0; jj < 16; jj++) {
            int j = slice*16 + jj;
            float2 w2 = *reinterpret_cast<const float2*>(&g_mlp2t[j*128 + oc0]);
            float4 a0 = *reinterpret_cast<const float4*>(&s.Out8[j*8]);
            float4 a1 = *reinterpret_cast<const float4*>(&s.Out8[j*8+4]);
            acc0[0] = fmaf(w2.x, a0.x, acc0[0]); acc1[0] = fmaf(w2.y, a0.x, acc1[0]);
            acc0[1] = fmaf(w2.x, a0.y, acc0[1]); acc1[1] = fmaf(w2.y, a0.y, acc1[1]);
            acc0[2] = fmaf(w2.x, a0.z, acc0[2]); acc1[2] = fmaf(w2.y, a0.z, acc1[2]);
            acc0[3] = fmaf(w2.x, a0.w, acc0[3]); acc1[3] = fmaf(w2.y, a0.w, acc1[3]);
            acc0[4] = fmaf(w2.x, a1.x, acc0[4]); acc1[4] = fmaf(w2.y, a1.x, acc1[4]);
            acc0[5] = fmaf(w2.x, a1.y, acc0[5]); acc1[5] = fmaf(w2.y, a1.y, acc1[5]);
            acc0[6] = fmaf(w2.x, a1.z, acc0[6]); acc1[6] = fmaf(w2.y, a1.z, acc1[6]);
            acc0[7] = fmaf(w2.x, a1.w, acc0[7]); acc1[7] = fmaf(w2.y, a1.w, acc1[7]);
        }
#pragma unroll
        for (int dd = 0; dd < 8; dd++) {
            int d = slice*8 + dd;
            float2 w2 = *reinterpret_cast<const float2*>(&g_scWt[d*128 + oc0]);
            float4 f0 = *reinterpret_cast<const float4*>(&s.Fe8[d*8]);
            float4 f1 = *reinterpret_cast<const float4*>(&s.Fe8[d*8+4]);
            acc0[0] = fmaf(w2.x, f0.x, acc0[0]); acc1[0] = fmaf(w2.y, f0.x, acc1[0]);
            acc0[1] = fmaf(w2.x, f0.y, acc0[1]); acc1[1] = fmaf(w2.y, f0.y, acc1[1]);
            acc0[2] = fmaf(w2.x, f0.z, acc0[2]); acc1[2] = fmaf(w2.y, f0.z, acc1[2]);
            acc0[3] = fmaf(w2.x, f0.w, acc0[3]); acc1[3] = fmaf(w2.y, f0.w, acc1[3]);
            acc0[4] = fmaf(w2.x, f1.x, acc0[4]); acc1[4] = fmaf(w2.y, f1.x, acc1[4]);
            acc0[5] = fmaf(w2.x, f1.y, acc0[5]); acc1[5] = fmaf(w2.y, f1.y, acc1[5]);
            acc0[6] = fmaf(w2.x, f1.z, acc0[6]); acc1[6] = fmaf(w2.y, f1.z, acc1[6]);
            acc0[7] = fmaf(w2.x, f1.w, acc0[7]); acc1[7] = fmaf(w2.y, f1.w, acc1[7]);
        }
        int b0 = (slice*128 + oc0)*8;
        *reinterpret_cast<float4*>(&s.Part[b0])     = make_float4(acc0[0], acc0[1], acc0[2], acc0[3]);
        *reinterpret_cast<float4*>(&s.Part[b0+4])   = make_float4(acc0[4], acc0[5], acc0[6], acc0[7]);
        *reinterpret_cast<float4*>(&s.Part[b0+8])   = make_float4(acc1[0], acc1[1], acc1[2], acc1[3]);
        *reinterpret_cast<float4*>(&s.Part[b0+12])  = make_float4(acc1[4], acc1[5], acc1[6], acc1[7]);
    }
    __syncthreads();

    {
        const float bns = rsqrtf(1.0f + 1e-5f);
        int oc = tid & 127;
        int ph = tid >> 7;
        float4 v = make_float4(0.f, 0.f, 0.f, 0.f);
#pragma unroll
        for (int sl = 0; sl < 4; sl++) {
            float4 t = *reinterpret_cast<const float4*>(&s.Part[(sl*128 + oc)*8 + ph*4]);
            v.x += t.x; v.y += t.y; v.z += t.z; v.w += t.w;
        }
        float basev = mlp2_b[oc] + sc_g[oc]*bns*sc_b[oc] + sc_bt[oc];
        v.x += basev; v.y += basev; v.z += basev; v.w += basev;
        v.x = v.x >= 0.f ? v.x : 0.01f*v.x;
        v.y = v.y >= 0.f ? v.y : 0.01f*v.y;
        v.z = v.z >= 0.f ? v.z : 0.01f*v.z;
        v.w = v.w >= 0.f ? v.w : 0.01f*v.w;

        int p0 = blockIdx.x * 8;
        int b0 = p0 >> 13, n0 = p0 & (NN - 1);
        *reinterpret_cast<float4*>(&out[((size_t)(b0*128 + oc))*NN + n0 + ph*4]) = v;
    }
}

// ---------------- launch ----------------
extern "C" void kernel_launch(void* const* d_in, const int* in_sizes, int n_in,
                              void* d_out, int out_size) {
    const float* coords   = (const float*)d_in[0];
    const float* features = (const float*)d_in[1];
    const float* mlp1_W = (const float*)d_in[2];
    const float* mlp1_b = (const float*)d_in[3];
    const float* lse1_W = (const float*)d_in[4];
    const float* lse1_b = (const float*)d_in[5];
    const float* lse1_g = (const float*)d_in[6];
    const float* lse1_bt = (const float*)d_in[7];
    const float* p1_Wc1 = (const float*)d_in[8];
    const float* p1_Wc2 = (const float*)d_in[9];
    const float* p1_Ws  = (const float*)d_in[10];
    const float* p1_Wm  = (const float*)d_in[11];
    const float* p1_bm  = (const float*)d_in[12];
    const float* p1_g   = (const float*)d_in[13];
    const float* p1_bt  = (const float*)d_in[14];
    const float* lse2_W = (const float*)d_in[15];
    const float* lse2_b = (const float*)d_in[16];
    const float* lse2_g = (const float*)d_in[17];
    const float* lse2_bt = (const float*)d_in[18];
    const float* p2_Wc1 = (const float*)d_in[19];
    const float* p2_Wc2 = (const float*)d_in[20];
    const float* p2_Ws  = (const float*)d_in[21];
    const float* p2_Wm  = (const float*)d_in[22];
    const float* p2_bm  = (const float*)d_in[23];
    const float* p2_g   = (const float*)d_in[24];
    const float* p2_bt  = (const float*)d_in[25];
    const float* mlp2_W = (const float*)d_in[26];
    const float* mlp2_b = (const float*)d_in[27];
    const float* sc_W   = (const float*)d_in[28];
    const float* sc_b   = (const float*)d_in[29];
    const float* sc_g   = (const float*)d_in[30];
    const float* sc_bt  = (const float*)d_in[31];
    float* out = (float*)d_out;

    int prep_blocks = 11 + (BB*NN)/32;
    prep_all<<<prep_blocks, 256>>>(mlp1_W, lse1_W, lse2_W, p1_Wc1, p1_Wc2, p1_Wm,
                                   p2_Wc1, p2_Wc2, p2_Wm, mlp2_W, sc_W, sc_g, features);
    knn_filter<<<dim3(NN/QPB, BB), 256>>>(coords);
    fused_kernel<<<(BB*NN)/8, 256>>>(coords, mlp1_b, lse1_b, lse1_g, lse1_bt,
                                     p1_Ws, p1_bm, p1_g, p1_bt,
                                     lse2_b, lse2_g, lse2_bt,
                                     p2_Ws, p2_bm, p2_g, p2_bt,
                                     mlp2_b, sc_b, sc_g, sc_bt, out);
}

// round 16
// speedup vs baseline: 3.2896x; 1.2689x over previous
#include <cuda_runtime.h>
#include <math.h>

#define BB 2
#define NN 8192
#define KNN 16
#define CIN 32
#define FULLW 0xffffffffu

// knn filter config
#define QPB 32      // queries per block
#define NSEG 8      // candidate segments (one warp of lanes per seg)
#define CAP 20      // buffer capacity per (query, segment)
#define ROWW (NSEG*CAP + 1)   // 161: padded row -> conflict-free
#define FTILE 512   // candidates staged per tile

// ---------------- scratch ----------------
__device__ float  g_feat_t[BB*NN*CIN];
__device__ float4 g_nb[BB*NN*KNN]; // (nx, ny, nz, dist) per point per k, ascending
// weights, repacked by prep
__device__ float g_mlp1Wt[32*32];
__device__ float g_lse1We[3*32];
__device__ float g_lse1Wn[4*32];
__device__ float g_lse2We[3*32];
__device__ float g_lse2Wn[4*32];
__device__ float g_p1c1p[512];
__device__ float g_p1c2p[512];
__device__ float g_p1wmt[64*32];
__device__ float g_p2c1p[512];
__device__ float g_p2c2p[512];
__device__ float g_p2wmt[64*64];
__device__ float g_mlp2t[64*128];
__device__ float g_scWt[32*128];   // pre-scaled by sc_g*bns

// ---------------- prep: weights + tiled feat transpose ----------------
__global__ void prep_all(
    const float* __restrict__ mlp1_W,
    const float* __restrict__ lse1_W,
    const float* __restrict__ lse2_W,
    const float* __restrict__ p1c1, const float* __restrict__ p1c2, const float* __restrict__ p1wm,
    const float* __restrict__ p2c1, const float* __restrict__ p2c2, const float* __restrict__ p2wm,
    const float* __restrict__ mlp2_W, const float* __restrict__ sc_W,
    const float* __restrict__ sc_g, const float* __restrict__ features)
{
    const float bns = rsqrtf(1.0f + 1e-5f);
    int t = threadIdx.x;
    int bid = blockIdx.x;
    if (bid < 11) {
        switch (bid) {
            case 0:
                for (int i = t; i < 32*32; i += 256) g_mlp1Wt[(i%32)*32 + (i/32)] = mlp1_W[i];
                break;
            case 1:
                if (t < 32) {
                    for (int d = 0; d < 3; d++) {
                        g_lse1We[d*32+t] = lse1_W[t*10+d]   + lse1_W[t*10+6+d];
                        g_lse1Wn[d*32+t] = lse1_W[t*10+3+d] - lse1_W[t*10+6+d];
                    }
                    g_lse1Wn[3*32+t] = lse1_W[t*10+9];
                }
                break;
            case 2:
                if (t < 32) {
                    for (int d = 0; d < 3; d++) {
                        g_lse2We[d*32+t] = lse2_W[t*10+d]   + lse2_W[t*10+6+d];
                        g_lse2Wn[d*32+t] = lse2_W[t*10+3+d] - lse2_W[t*10+6+d];
                    }
                    g_lse2Wn[3*32+t] = lse2_W[t*10+9];
                }
                break;
            case 3:
                for (int i = t; i < 512; i += 256) {
                    int j = i / 64, c = i % 64;
                    g_p1c1p[((c>>2)*8 + j)*4 + (c&3)] = p1c1[i];
                }
                break;
            case 4:
                for (int i = t; i < 512; i += 256) {
                    int r = i / 8, c = i % 8;
                    g_p1c2p[((c>>2)*64 + r)*4 + (c&3)] = p1c2[i];
                }
                break;
            case 5:
                for (int i = t; i < 32*64; i += 256) g_p1wmt[(i%64)*32 + (i/64)] = p1wm[i];
                break;
            case 6:
                for (int i = t; i < 512; i += 256) {
                    int j = i / 64, c = i % 64;
                    g_p2c1p[((c>>2)*8 + j)*4 + (c&3)] = p2c1[i];
                }
                break;
            case 7:
                for (int i = t; i < 512; i += 256) {
                    int r = i / 8, c = i % 8;
                    g_p2c2p[((c>>2)*64 + r)*4 + (c&3)] = p2c2[i];
                }
                break;
            case 8:
                for (int i = t; i < 64*64; i += 256) g_p2wmt[(i%64)*64 + (i/64)] = p2wm[i];
                break;
            case 9:
                for (int i = t; i < 128*64; i += 256) g_mlp2t[(i%64)*128 + (i/64)] = mlp2_W[i];
                break;
            default:
                for (int i = t; i < 128*32; i += 256) {
                    int oc = i / 32, d = i % 32;
                    g_scWt[d*128 + oc] = sc_W[i] * sc_g[oc] * bns;
                }
                break;
        }
        return;
    }
    // tiled feat transpose: 32 n x 32 c per block, both sides coalesced
    {
        __shared__ float tile[32][33];
        int tb = bid - 11;
        int b = tb / (NN/32);
        int n0 = (tb % (NN/32)) * 32;
        int w = t >> 5, l = t & 31;
        for (int cc = w; cc < 32; cc += 8)
            tile[cc][l] = features[((size_t)b*CIN + cc)*NN + n0 + l];
        __syncthreads();
        for (int nn = w; nn < 32; nn += 8)
            g_feat_t[((size_t)b*NN + n0 + nn)*CIN + l] = tile[l][nn];
    }
}

// ---------------- bitonic helpers ----------------
__device__ __forceinline__ void bitonic32(float& key, int& pay, int lane) {
#pragma unroll
    for (int k = 2; k <= 32; k <<= 1) {
#pragma unroll
        for (int j = k >> 1; j > 0; j >>= 1) {
            float ok = __shfl_xor_sync(FULLW, key, j);
            int   op = __shfl_xor_sync(FULLW, pay, j);
            bool takeMin = (((lane & j) == 0) == ((lane & k) == 0));
            bool less = (ok < key) || (ok == key && op < pay);
            if (takeMin ? less : !less) { key = ok; pay = op; }
        }
    }
}

__device__ __forceinline__ void merge_chunk(
    float key, int pay, float& lv, int& li, int lane)
{
    float ck = __shfl_xor_sync(FULLW, key, 31);
    int   cp = __shfl_xor_sync(FULLW, pay, 31);
    float v  = (lane < 16) ? lv : ck;
    int   vp = (lane < 16) ? li : cp;
#pragma unroll
    for (int j = 16; j > 0; j >>= 1) {
        float ov  = __shfl_xor_sync(FULLW, v, j);
        int   ovp = __shfl_xor_sync(FULLW, vp, j);
        bool takeMin = ((lane & j) == 0);
        bool less = (ov < v) || (ov == v && ovp < vp);
        if (takeMin ? less : !less) { v = ov; vp = ovp; }
    }
    lv = v; li = vp;
}

// warp-cooperative exact scan (fallback; proven R9-R15 machinery; now ~never taken)
__device__ void exact_knn_warp(
    const float* __restrict__ cb, float qx, float qy, float qz,
    int lane, float& outLv, int& outLi)
{
    float lv = 3.4e38f; int li = 0x7fffffff;
    float tauV = 3.4e38f; int tauI = 0x7fffffff;
    bool seeded = false;
    for (int f = 0; f < NN; f += 32) {
        int j = f + lane;
        float x = cb[3*j], y = cb[3*j+1], z = cb[3*j+2];
        float dx = qx-x, dy = qy-y, dz = qz-z;
        float d2 = fmaf(dx, dx, fmaf(dy, dy, dz*dz));
        if (!seeded) {
            float key = d2; int pay = j;
            bitonic32(key, pay, lane);
            lv = (lane < 16) ? key : 3.4e38f;
            li = pay;
            tauV = __shfl_sync(FULLW, key, 15);
            tauI = __shfl_sync(FULLW, pay, 15);
            seeded = true;
            continue;
        }
        unsigned m = __ballot_sync(FULLW, (d2 < tauV) || (d2 == tauV && j < tauI));
        while (m) {
            int src = __ffs(m) - 1;
            m &= m - 1;
            float v  = __shfl_sync(FULLW, d2, src);
            int   vj = __shfl_sync(FULLW, j, src);
            if ((v < tauV) || (v == tauV && vj < tauI)) {
                unsigned le = __ballot_sync(FULLW,
                    (lane < 16) && ((lv < v) || (lv == v && li < vj)));
                int pos = __popc(le);
                float upv = __shfl_up_sync(FULLW, lv, 1);
                int   upi = __shfl_up_sync(FULLW, li, 1);
                if (lane == pos)                  { lv = v;   li = vj;  }
                else if (lane > pos && lane < 16) { lv = upv; li = upi; }
                tauV = __shfl_sync(FULLW, lv, 15);
                tauI = __shfl_sync(FULLW, li, 15);
            }
        }
    }
    outLv = lv; outLi = li;
}

// ---------------- KNN: radius filter (exact noncentral-chi sizing) + bitonic selection ----------------
__global__ void __launch_bounds__(256) knn_filter(const float* __restrict__ coords) {
    __shared__ float4 tile[FTILE];                  // 8 KB
    __shared__ float          sd2[QPB][ROWW];       // 20.6 KB
    __shared__ unsigned short sidx[QPB][ROWW];      // 10.3 KB
    __shared__ int            scnt[NSEG][QPB];      // 1 KB

    int tid = threadIdx.x;
    int b = blockIdx.y;
    int qbase = blockIdx.x * QPB;
    int ql = tid & (QPB-1);
    int seg = tid >> 5;
    int n = qbase + ql;
    const float* cb = coords + (size_t)b*NN*3;

    float qx = cb[n*3+0], qy = cb[n*3+1], qz = cb[n*3+2];
    float qsq = qx*qx + qy*qy + qz*qz;

    // Radius from EXACT expected in-ball count for N(0,I3):
    // F(d,R) = Phi(R-d) + Phi(R+d) - 1 + (exp(-(R+d)^2/2) - exp(-(R-d)^2/2)) / (d*sqrt(2pi))
    // Solve F = 56/8192 by bisection -> expected 56 candidates for EVERY query position.
    float d = fmaxf(sqrtf(qsq), 1e-3f);
    const float target = 56.0f / 8192.0f;
    float lo = 0.05f, hi = 4.0f;
#pragma unroll 1
    for (int it = 0; it < 14; it++) {
        float Rm = 0.5f*(lo + hi);
        float a = Rm - d, bb2 = Rm + d;
        float F = 0.5f*(erff(a*0.70710678f) + erff(bb2*0.70710678f))
                + (__expf(-0.5f*bb2*bb2) - __expf(-0.5f*a*a)) * (0.39894228f/d);
        if (F < target) lo = Rm; else hi = Rm;
    }
    float R = hi;
    float tau = R*R - qsq;   // compare d2' = (|c|^2 - 2 q.c) < tau
    int cnt = 0;
    float* rowD = &sd2[ql][seg*CAP];
    unsigned short* rowI = &sidx[ql][seg*CAP];

    for (int t0 = 0; t0 < NN; t0 += FTILE) {
        __syncthreads();
        for (int u = tid; u < FTILE; u += 256) {
            int j = t0 + u;
            float x = cb[j*3+0], y = cb[j*3+1], z = cb[j*3+2];
            tile[u] = make_float4(-2.0f*x, -2.0f*y, -2.0f*z, x*x + y*y + z*z);
        }
        __syncthreads();

        int base = seg * (FTILE/NSEG);
#pragma unroll 4
        for (int e = 0; e < FTILE/NSEG; e++) {
            float4 c = tile[base + e];   // broadcast
            float d2 = fmaf(qx, c.x, fmaf(qy, c.y, fmaf(qz, c.z, c.w)));
            if (d2 < tau) {
                int cc = min(cnt, CAP-1);   // clamped; corruption only if flagged
                rowD[cc] = d2;
                rowI[cc] = (unsigned short)(t0 + base + e);
                cnt++;
            }
        }
    }
    scnt[seg][ql] = cnt;
    __syncthreads();

    // ---- selection: warp per query, bitonic top-16 ----
    int warp = tid >> 5, lane = tid & 31;
    for (int it = 0; it < QPB/8; it++) {
        int q = warp*(QPB/8) + it;
        int qn = qbase + q;
        int cs[NSEG];
        bool over = false;
        int tot = 0;
#pragma unroll
        for (int k = 0; k < NSEG; k++) {
            cs[k] = scnt[k][q];
            over |= (cs[k] > CAP);
            tot += cs[k];
        }
        float fqx = cb[qn*3+0], fqy = cb[qn*3+1], fqz = cb[qn*3+2];

        float lv; int li;
        if (over || tot < KNN) {
            exact_knn_warp(cb, fqx, fqy, fqz, lane, lv, li);
        } else {
            float key; int pay;
            {
                int e = lane;
                key = 3.4e38f; pay = 0x7fffffff;
                int acc = 0;
#pragma unroll
                for (int k = 0; k < NSEG; k++) {
                    if (e >= acc && e < acc + cs[k]) {
                        key = sd2[q][k*CAP + (e - acc)];
                        pay = sidx[q][k*CAP + (e - acc)];
                    }
                    acc += cs[k];
                }
            }
            bitonic32(key, pay, lane);
            lv = (lane < 16) ? key : 3.4e38f;
            li = pay;
            for (int cb2 = 32; cb2 < tot; cb2 += 32) {
                int e = cb2 + lane;
                key = 3.4e38f; pay = 0x7fffffff;
                int acc = 0;
#pragma unroll
                for (int k = 0; k < NSEG; k++) {
                    if (e >= acc && e < acc + cs[k]) {
                        key = sd2[q][k*CAP + (e - acc)];
                        pay = sidx[q][k*CAP + (e - acc)];
                    }
                    acc += cs[k];
                }
                bitonic32(key, pay, lane);
                merge_chunk(key, pay, lv, li, lane);
            }
        }

        if (lane < KNN) {
            int j = li;
            float nx = cb[j*3+0], ny = cb[j*3+1], nz = cb[j*3+2];
            float dx = fqx-nx, dy = fqy-ny, dz = fqz-nz;
            g_nb[((size_t)b*NN + qn)*KNN + lane] =
                make_float4(nx, ny, nz, sqrtf(fmaf(dx, dx, fmaf(dy, dy, dz*dz))));
        }
    }
}

// ---------------- fused per-point pipeline (8 points per 256-thread block) ----------------
__device__ __forceinline__ float sigmoidf_(float x) { return 1.0f / (1.0f + expf(-x)); }

struct SArena {
    float4 nb[8][16];
    float  A[8][64];
    float  M[8][64];
    float  Hs[8][8];
    float  Sp[8][16];
    float  Fe8[32*8];
    float  F8[64*8];
    float  Out8[64*8];
    float  Part[4096];
};

template<int NOUT>
__device__ __forceinline__ void stage(
    SArena* s, float featv, float cx, float cy, float cz,
    const float* __restrict__ We, const float* __restrict__ Wn,
    const float* __restrict__ bl, const float* __restrict__ gl, const float* __restrict__ btl,
    const float* __restrict__ c1p, const float* __restrict__ c2p,
    const float* __restrict__ Ws,
    const float* __restrict__ Wmt, const float* __restrict__ bm,
    const float* __restrict__ gm,  const float* __restrict__ btm,
    int lane, int warp, int tid)
{
    const float bns = rsqrtf(1.0f + 1e-5f);
    float we0 = We[0*32+lane], we1 = We[1*32+lane], we2 = We[2*32+lane];
    float wn0 = Wn[0*32+lane], wn1 = Wn[1*32+lane], wn2 = Wn[2*32+lane], wn3 = Wn[3*32+lane];
    float scl = gl[lane]*bns, shb = btl[lane];
    float base = bl[lane];
    base = fmaf(we0, cx, fmaf(we1, cy, fmaf(we2, cz, base)));

    float e[16];
    float avg = 0.f, mx = -3.4e38f;
#pragma unroll
    for (int k = 0; k < 16; k++) {
        float4 nb = s->nb[warp][k];
        float v = fmaf(wn0, nb.x, fmaf(wn1, nb.y, fmaf(wn2, nb.z, fmaf(wn3, nb.w, base))));
        v = fmaxf(scl*v + shb, 0.f);
        e[k] = v;
        avg += v;
        mx = fmaxf(mx, v);
    }
    avg *= 0.0625f;
    s->A[warp][lane] = avg; s->A[warp][32 + lane] = featv;
    s->M[warp][lane] = mx;  s->M[warp][32 + lane] = featv;
    __syncwarp();

    {
        int j = lane & 7;
        int srcbit = (lane >> 3) & 1;
        int chalf = lane >> 4;
        const float* S = srcbit ? s->M[warp] : s->A[warp];
        float h = 0.f;
#pragma unroll
        for (int cq = 0; cq < 8; cq++) {
            int quad = chalf*8 + cq;
            float4 w4 = *reinterpret_cast<const float4*>(&c1p[(quad*8 + j)*4]);
            float4 a4 = *reinterpret_cast<const float4*>(&S[chalf*32 + cq*4]);
            h = fmaf(w4.x, a4.x, fmaf(w4.y, a4.y, fmaf(w4.z, a4.z, fmaf(w4.w, a4.w, h))));
        }
        h += __shfl_xor_sync(FULLW, h, 16);
        float h2 = fmaxf(h, 0.f);
        float hsv = h2 + __shfl_xor_sync(FULLW, h2, 8);
        if (lane < 8) s->Hs[warp][lane] = hsv;
    }
    __syncwarp();

    float4 hs0 = *reinterpret_cast<const float4*>(&s->Hs[warp][0]);
    float4 hs1 = *reinterpret_cast<const float4*>(&s->Hs[warp][4]);
    float a, b2;
    {
        float4 w0 = *reinterpret_cast<const float4*>(&c2p[lane*4]);
        float4 w1 = *reinterpret_cast<const float4*>(&c2p[(64 + lane)*4]);
        a = w0.x*hs0.x + w0.y*hs0.y + w0.z*hs0.z + w0.w*hs0.w
          + w1.x*hs1.x + w1.y*hs1.y + w1.z*hs1.z + w1.w*hs1.w;
        float4 v0 = *reinterpret_cast<const float4*>(&c2p[(32 + lane)*4]);
        float4 v1 = *reinterpret_cast<const float4*>(&c2p[(96 + lane)*4]);
        b2 = v0.x*hs0.x + v0.y*hs0.y + v0.z*hs0.z + v0.w*hs0.w
           + v1.x*hs1.x + v1.y*hs1.y + v1.z*hs1.z + v1.w*hs1.w;
    }
    float chA = sigmoidf_(a), chB = sigmoidf_(b2);
    float xf = featv * chB;

    float vs[16], vm[16];
#pragma unroll
    for (int k = 0; k < 16; k++) {
        float ek = e[k] * chA;
        e[k] = ek;
        vs[k] = ek + xf;
        vm[k] = fmaxf(ek, xf);
    }
    {
        bool up = (lane & 16);
#pragma unroll
        for (int i = 0; i < 8; i++) {
            float ss = up ? vs[i] : vs[i+8];
            float ks = up ? vs[i+8] : vs[i];
            vs[i] = ks + __shfl_xor_sync(FULLW, ss, 16);
            float sm2 = up ? vm[i] : vm[i+8];
            float km = up ? vm[i+8] : vm[i];
            vm[i] = fmaxf(km, __shfl_xor_sync(FULLW, sm2, 16));
        }
    }
    {
        bool up = (lane & 8);
#pragma unroll
        for (int i = 0; i < 4; i++) {
            float ss = up ? vs[i] : vs[i+4];
            float ks = up ? vs[i+4] : vs[i];
            vs[i] = ks + __shfl_xor_sync(FULLW, ss, 8);
            float sm2 = up ? vm[i] : vm[i+4];
            float km = up ? vm[i+4] : vm[i];
            vm[i] = fmaxf(km, __shfl_xor_sync(FULLW, sm2, 8));
        }
    }
    {
        bool up = (lane & 4);
#pragma unroll
        for (int i = 0; i < 2; i++) {
            float ss = up ? vs[i] : vs[i+2];
            float ks = up ? vs[i+2] : vs[i];
            vs[i] = ks + __shfl_xor_sync(FULLW, ss, 4);
            float sm2 = up ? vm[i] : vm[i+2];
            float km = up ? vm[i+2] : vm[i];
            vm[i] = fmaxf(km, __shfl_xor_sync(FULLW, sm2, 4));
        }
    }
    {
        bool up = (lane & 2);
        float ss = up ? vs[0] : vs[1];
        float ks = up ? vs[1] : vs[0];
        vs[0] = ks + __shfl_xor_sync(FULLW, ss, 2);
        float sm2 = up ? vm[0] : vm[1];
        float km = up ? vm[1] : vm[0];
        vm[0] = fmaxf(km, __shfl_xor_sync(FULLW, sm2, 2));
    }
    vs[0] += __shfl_xor_sync(FULLW, vs[0], 1);
    vm[0] = fmaxf(vm[0], __shfl_xor_sync(FULLW, vm[0], 1));

    float ws0 = Ws[0], ws1 = Ws[1];
    float sp = sigmoidf_(ws0 * vs[0] * (1.0f/64.0f) + ws1 * vm[0]);
    int kL = (((lane>>4)&1)<<3) | (((lane>>3)&1)<<2) | (((lane>>2)&1)<<1) | ((lane>>1)&1);
    if (!(lane & 1)) s->Sp[warp][kL] = sp;
    float sps = sp;
#pragma unroll
    for (int off = 16; off > 0; off >>= 1) sps += __shfl_xor_sync(FULLW, sps, off);
    sps *= 0.5f;
    __syncwarp();

    float fA = 0.f;
#pragma unroll
    for (int k = 0; k < 16; k++) fA = fmaf(e[k], s->Sp[warp][k], fA);

    s->F8[lane*8 + warp]        = fA;
    s->F8[(32 + lane)*8 + warp] = xf * sps;
    __syncthreads();

    constexpr int G = NOUT/32;
    {
        float acc[G][8];
#pragma unroll
        for (int g = 0; g < G; g++)
#pragma unroll
            for (int p = 0; p < 8; p++) acc[g][p] = 0.f;
        int jb = warp * 8;
#pragma unroll
        for (int jj = 0; jj < 8; jj++) {
            int j = jb + jj;
            float4 a0 = *reinterpret_cast<const float4*>(&s->F8[j*8]);
            float4 a1 = *reinterpret_cast<const float4*>(&s->F8[j*8+4]);
#pragma unroll
            for (int g = 0; g < G; g++) {
                float wv = Wmt[j*NOUT + g*32 + lane];
                acc[g][0] = fmaf(wv, a0.x, acc[g][0]);
                acc[g][1] = fmaf(wv, a0.y, acc[g][1]);
                acc[g][2] = fmaf(wv, a0.z, acc[g][2]);
                acc[g][3] = fmaf(wv, a0.w, acc[g][3]);
                acc[g][4] = fmaf(wv, a1.x, acc[g][4]);
                acc[g][5] = fmaf(wv, a1.y, acc[g][5]);
                acc[g][6] = fmaf(wv, a1.z, acc[g][6]);
                acc[g][7] = fmaf(wv, a1.w, acc[g][7]);
            }
        }
#pragma unroll
        for (int g = 0; g < G; g++) {
            int bidx = (warp*NOUT + g*32 + lane)*8;
            *reinterpret_cast<float4*>(&s->Part[bidx])   = make_float4(acc[g][0], acc[g][1], acc[g][2], acc[g][3]);
            *reinterpret_cast<float4*>(&s->Part[bidx+4]) = make_float4(acc[g][4], acc[g][5], acc[g][6], acc[g][7]);
        }
    }
    __syncthreads();

#pragma unroll
    for (int g = 0; g < G; g++) {
        int idx = g*256 + tid;
        int oc = idx >> 3, pp = idx & 7;
        float sum = 0.f;
#pragma unroll
        for (int w = 0; w < 8; w++) sum += s->Part[(w*NOUT + oc)*8 + pp];
        sum += bm[oc];
        s->Out8[idx] = fmaxf(gm[oc]*bns*sum + btm[oc], 0.f);
    }
    __syncthreads();
}

__global__ void __launch_bounds__(256) fused_kernel(
    const float* __restrict__ coords,
    const float* __restrict__ mlp1_b,
    const float* __restrict__ lse1_b, const float* __restrict__ lse1_g, const float* __restrict__ lse1_bt,
    const float* __restrict__ p1_Ws,  const float* __restrict__ p1_bm,  const float* __restrict__ p1_g, const float* __restrict__ p1_bt,
    const float* __restrict__ lse2_b, const float* __restrict__ lse2_g, const float* __restrict__ lse2_bt,
    const float* __restrict__ p2_Ws,  const float* __restrict__ p2_bm,  const float* __restrict__ p2_g, const float* __restrict__ p2_bt,
    const float* __restrict__ mlp2_b,
    const float* __restrict__ sc_b, const float* __restrict__ sc_g, const float* __restrict__ sc_bt,
    float* __restrict__ out)
{
    __shared__ SArena s;

    int tid = threadIdx.x;
    int warp = tid >> 5, lane = tid & 31;
    int p = blockIdx.x * 8 + warp;
    int b = p >> 13, n = p & (NN - 1);

    s.Fe8[lane*8 + warp] = g_feat_t[p*CIN + lane];

    const float* cb = coords + ((size_t)b*NN + n)*3;
    float cx = cb[0], cy = cb[1], cz = cb[2];
    if (lane < 16) {
        s.nb[warp][lane] = g_nb[(size_t)p*KNN + lane];
    }
    __syncwarp();

    float x1;
    {
        float acc = mlp1_b[lane];
#pragma unroll
        for (int d = 0; d < 32; d++) acc = fmaf(g_mlp1Wt[d*32 + lane], s.Fe8[d*8 + warp], acc);
        x1 = acc >= 0.f ? acc : 0.2f*acc;
    }

    stage<32>(&s, x1, cx, cy, cz, g_lse1We, g_lse1Wn, lse1_b, lse1_g, lse1_bt,
              g_p1c1p, g_p1c2p, p1_Ws, g_p1wmt, p1_bm, p1_g, p1_bt, lane, warp, tid);
    float o1 = s.Out8[lane*8 + warp];

    stage<64>(&s, o1, cx, cy, cz, g_lse2We, g_lse2Wn, lse2_b, lse2_g, lse2_bt,
              g_p2c1p, g_p2c2p, p2_Ws, g_p2wmt, p2_bm, p2_g, p2_bt, lane, warp, tid);

    {
        int slice = tid >> 6;
        int oc0 = (tid & 63) * 2;
        float acc0[8], acc1[8];
#pragma unroll
        for (int q = 0; q < 8; q++) { acc0[q] = 0.f; acc1[q] = 0.f; }
#pragma unroll
        for (int jj = 0; jj < 16; jj++) {
            int j = slice*16 + jj;
            float2 w2 = *reinterpret_cast<const float2*>(&g_mlp2t[j*128 + oc0]);
            float4 a0 = *reinterpret_cast<const float4*>(&s.Out8[j*8]);
            float4 a1 = *reinterpret_cast<const float4*>(&s.Out8[j*8+4]);
            acc0[0] = fmaf(w2.x, a0.x, acc0[0]); acc1[0] = fmaf(w2.y, a0.x, acc1[0]);
            acc0[1] = fmaf(w2.x, a0.y, acc0[1]); acc1[1] = fmaf(w2.y, a0.y, acc1[1]);
            acc0[2] = fmaf(w2.x, a0.z, acc0[2]); acc1[2] = fmaf(w2.y, a0.z, acc1[2]);
            acc0[3] = fmaf(w2.x, a0.w, acc0[3]); acc1[3] = fmaf(w2.y, a0.w, acc1[3]);
            acc0[4] = fmaf(w2.x, a1.x, acc0[4]); acc1[4] = fmaf(w2.y, a1.x, acc1[4]);
            acc0[5] = fmaf(w2.x, a1.y, acc0[5]); acc1[5] = fmaf(w2.y, a1.y, acc1[5]);
            acc0[6] = fmaf(w2.x, a1.z, acc0[6]); acc1[6] = fmaf(w2.y, a1.z, acc1[6]);
            acc0[7] = fmaf(w2.x, a1.w, acc0[7]); acc1[7] = fmaf(w2.y, a1.w, acc1[7]);
        }
#pragma unroll
        for (int dd = 0; dd < 8; dd++) {
            int d = slice*8 + dd;
            float2 w2 = *reinterpret_cast<const float2*>(&g_scWt[d*128 + oc0]);
            float4 f0 = *reinterpret_cast<const float4*>(&s.Fe8[d*8]);
            float4 f1 = *reinterpret_cast<const float4*>(&s.Fe8[d*8+4]);
            acc0[0] = fmaf(w2.x, f0.x, acc0[0]); acc1[0] = fmaf(w2.y, f0.x, acc1[0]);
            acc0[1] = fmaf(w2.x, f0.y, acc0[1]); acc1[1] = fmaf(w2.y, f0.y, acc1[1]);
            acc0[2] = fmaf(w2.x, f0.z, acc0[2]); acc1[2] = fmaf(w2.y, f0.z, acc1[2]);
            acc0[3] = fmaf(w2.x, f0.w, acc0[3]); acc1[3] = fmaf(w2.y, f0.w, acc1[3]);
            acc0[4] = fmaf(w2.x, f1.x, acc0[4]); acc1[4] = fmaf(w2.y, f1.x, acc1[4]);
            acc0[5] = fmaf(w2.x, f1.y, acc0[5]); acc1[5] = fmaf(w2.y, f1.y, acc1[5]);
            acc0[6] = fmaf(w2.x, f1.z, acc0[6]); acc1[6] = fmaf(w2.y, f1.z, acc1[6]);
            acc0[7] = fmaf(w2.x, f1.w, acc0[7]); acc1[7] = fmaf(w2.y, f1.w, acc1[7]);
        }
        int b0 = (slice*128 + oc0)*8;
        *reinterpret_cast<float4*>(&s.Part[b0])     = make_float4(acc0[0], acc0[1], acc0[2], acc0[3]);
        *reinterpret_cast<float4*>(&s.Part[b0+4])   = make_float4(acc0[4], acc0[5], acc0[6], acc0[7]);
        *reinterpret_cast<float4*>(&s.Part[b0+8])   = make_float4(acc1[0], acc1[1], acc1[2], acc1[3]);
        *reinterpret_cast<float4*>(&s.Part[b0+12])  = make_float4(acc1[4], acc1[5], acc1[6], acc1[7]);
    }
    __syncthreads();

    {
        const float bns = rsqrtf(1.0f + 1e-5f);
        int oc = tid & 127;
        int ph = tid >> 7;
        float4 v = make_float4(0.f, 0.f, 0.f, 0.f);
#pragma unroll
        for (int sl = 0; sl < 4; sl++) {
            float4 t = *reinterpret_cast<const float4*>(&s.Part[(sl*128 + oc)*8 + ph*4]);
            v.x += t.x; v.y += t.y; v.z += t.z; v.w += t.w;
        }
        float basev = mlp2_b[oc] + sc_g[oc]*bns*sc_b[oc] + sc_bt[oc];
        v.x += basev; v.y += basev; v.z += basev; v.w += basev;
        v.x = v.x >= 0.f ? v.x : 0.01f*v.x;
        v.y = v.y >= 0.f ? v.y : 0.01f*v.y;
        v.z = v.z >= 0.f ? v.z : 0.01f*v.z;
        v.w = v.w >= 0.f ? v.w : 0.01f*v.w;

        int p0 = blockIdx.x * 8;
        int b0 = p0 >> 13, n0 = p0 & (NN - 1);
        *reinterpret_cast<float4*>(&out[((size_t)(b0*128 + oc))*NN + n0 + ph*4]) = v;
    }
}

// ---------------- launch ----------------
extern "C" void kernel_launch(void* const* d_in, const int* in_sizes, int n_in,
                              void* d_out, int out_size) {
    const float* coords   = (const float*)d_in[0];
    const float* features = (const float*)d_in[1];
    const float* mlp1_W = (const float*)d_in[2];
    const float* mlp1_b = (const float*)d_in[3];
    const float* lse1_W = (const float*)d_in[4];
    const float* lse1_b = (const float*)d_in[5];
    const float* lse1_g = (const float*)d_in[6];
    const float* lse1_bt = (const float*)d_in[7];
    const float* p1_Wc1 = (const float*)d_in[8];
    const float* p1_Wc2 = (const float*)d_in[9];
    const float* p1_Ws  = (const float*)d_in[10];
    const float* p1_Wm  = (const float*)d_in[11];
    const float* p1_bm  = (const float*)d_in[12];
    const float* p1_g   = (const float*)d_in[13];
    const float* p1_bt  = (const float*)d_in[14];
    const float* lse2_W = (const float*)d_in[15];
    const float* lse2_b = (const float*)d_in[16];
    const float* lse2_g = (const float*)d_in[17];
    const float* lse2_bt = (const float*)d_in[18];
    const float* p2_Wc1 = (const float*)d_in[19];
    const float* p2_Wc2 = (const float*)d_in[20];
    const float* p2_Ws  = (const float*)d_in[21];
    const float* p2_Wm  = (const float*)d_in[22];
    const float* p2_bm  = (const float*)d_in[23];
    const float* p2_g   = (const float*)d_in[24];
    const float* p2_bt  = (const float*)d_in[25];
    const float* mlp2_W = (const float*)d_in[26];
    const float* mlp2_b = (const float*)d_in[27];
    const float* sc_W   = (const float*)d_in[28];
    const float* sc_b   = (const float*)d_in[29];
    const float* sc_g   = (const float*)d_in[30];
    const float* sc_bt  = (const float*)d_in[31];
    float* out = (float*)d_out;

    int prep_blocks = 11 + (BB*NN)/32;
    prep_all<<<prep_blocks, 256>>>(mlp1_W, lse1_W, lse2_W, p1_Wc1, p1_Wc2, p1_Wm,
                                   p2_Wc1, p2_Wc2, p2_Wm, mlp2_W, sc_W, sc_g, features);
    knn_filter<<<dim3(NN/QPB, BB), 256>>>(coords);
    fused_kernel<<<(BB*NN)/8, 256>>>(coords, mlp1_b, lse1_b, lse1_g, lse1_bt,
                                     p1_Ws, p1_bm, p1_g, p1_bt,
                                     lse2_b, lse2_g, lse2_bt,
                                     p2_Ws, p2_bm, p2_g, p2_bt,
                                     mlp2_b, sc_b, sc_g, sc_bt, out);
}